// round 1
// baseline (speedup 1.0000x reference)
#include <cuda_runtime.h>
#include <cstdint>

#define B       8
#define NA      100800
#define NC      85
#define K_PRE   1024
#define MAX_DET 100
#define NBINS   8192
#define CAP     2048
#define SORT_N  2048
#define CONF    0.25f
#define IOU_T   0.45f
#define MAXWH   7680.0f

// ---------------- device scratch (no allocations allowed) ----------------
__device__ uint32_t           g_keys[B * NA];
__device__ uint8_t            g_cls [B * NA];
__device__ uint32_t           g_hist[B * NBINS];
__device__ int                g_T   [B];
__device__ int                g_cnt [B];
__device__ unsigned long long g_cand[B * CAP];

// ---------------- kernel 0: zero histogram + counters ----------------
__global__ void zero_kernel() {
    int i = blockIdx.x * blockDim.x + threadIdx.x;
    if (i < B * NBINS) g_hist[i] = 0u;
    if (i < B)         g_cnt[i]  = 0;
}

// ---------------- kernel 1: per-anchor score / cls (warp per anchor) ----------------
__global__ void score_kernel(const float* __restrict__ pred) {
    int warp = (blockIdx.x * blockDim.x + threadIdx.x) >> 5;
    int lane = threadIdx.x & 31;
    if (warp >= B * NA) return;

    const float* p = pred + (size_t)warp * NC;
    float v1 = p[lane];                              // idx 0..31
    float v2 = p[32 + lane];                         // idx 32..63
    float v3 = (lane < 21) ? p[64 + lane] : 0.0f;    // idx 64..84

    const unsigned F = 0xffffffffu;
    float obj = __shfl_sync(F, v1, 4);

    // per-class product (rounded exactly like reference: pred[:,5:]*obj then max)
    float best = -1.0f; int bid = 0;
    if (lane >= 5) { best = __fmul_rn(v1, obj); bid = lane - 5; }
    {
        float c2 = __fmul_rn(v2, obj);
        if (c2 > best) { best = c2; bid = lane + 27; }
    }
    if (lane < 21) {
        float c3 = __fmul_rn(v3, obj);
        if (c3 > best) { best = c3; bid = lane + 59; }
    }
    // warp argmax, ties -> smaller class index (JAX argmax semantics)
    for (int o = 16; o; o >>= 1) {
        float ov = __shfl_xor_sync(F, best, o);
        int   oi = __shfl_xor_sync(F, bid,  o);
        if (ov > best || (ov == best && oi < bid)) { best = ov; bid = oi; }
    }

    if (lane == 0) {
        bool valid = (obj > CONF) && (best > CONF);
        g_keys[warp] = valid ? __float_as_uint(best) : 0u;
        g_cls [warp] = (uint8_t)bid;
        if (valid) {
            int b = warp / NA;
            int bin = (int)(best * (float)NBINS);
            if (bin > NBINS - 1) bin = NBINS - 1;
            atomicAdd(&g_hist[b * NBINS + bin], 1u);
        }
    }
}

// ---------------- kernel 2: per-batch threshold bin (top-K cutoff) ----------------
__global__ void thresh_kernel() {
    int b = blockIdx.x;
    int lane = threadIdx.x;
    const unsigned F = 0xffffffffu;
    int acc = 0;
    int T = 0;
    for (int hi = NBINS - 1; hi >= 31; hi -= 32) {
        int c = (int)g_hist[b * NBINS + hi - lane];
        int ps = c;
        for (int o = 1; o < 32; o <<= 1) {
            int v = __shfl_up_sync(F, ps, o);
            if (lane >= o) ps += v;
        }
        int tot = __shfl_sync(F, ps, 31);
        unsigned bal = __ballot_sync(F, acc + ps >= K_PRE);
        if (bal) { int l = __ffs(bal) - 1; T = hi - l; break; }
        acc += tot;
    }
    if (lane == 0) g_T[b] = T;
}

// ---------------- kernel 3: gather candidates >= threshold ----------------
__global__ void gather_kernel() {
    int i = blockIdx.x * blockDim.x + threadIdx.x;
    if (i >= B * NA) return;
    uint32_t key = g_keys[i];
    if (!key) return;
    int b = i / NA;
    float s = __uint_as_float(key);
    int bin = (int)(s * (float)NBINS);
    if (bin > NBINS - 1) bin = NBINS - 1;
    if (bin < g_T[b]) return;
    int pos = atomicAdd(&g_cnt[b], 1);
    if (pos < CAP) {
        uint32_t li = (uint32_t)(i - b * NA);
        // composite: descending score, ascending index on ties
        g_cand[b * CAP + pos] =
            ((unsigned long long)key << 32) | (unsigned long long)(0xFFFFFFFFu - li);
    }
}

// ---------------- kernel 4: sort + NMS + output (one block per batch) ----------------
__global__ void __launch_bounds__(1024, 1)
nms_kernel(const float* __restrict__ pred, float* __restrict__ out) {
    int b = blockIdx.x;
    int t = threadIdx.x;

    extern __shared__ unsigned char sm[];
    uint32_t*           maskC   = (uint32_t*)sm;                 // [32][1024] transposed, 128KB
    unsigned long long* sortbuf = (unsigned long long*)sm;       // aliases first 16KB (consumed before mask)
    float4*             boxoff  = (float4*)(sm + 32 * 1024 * 4); // 16KB

    __shared__ float    area_s[1024];
    __shared__ uint32_t keep_s[32];
    __shared__ int      pfx[33];

    // zero this batch's output region (d_out is poisoned)
    if (t < MAX_DET * 6) out[b * MAX_DET * 6 + t] = 0.0f;

    int cnt = g_cnt[b];
    if (cnt > CAP) cnt = CAP;

    // load flipped keys (ascending sort of ~key == descending sort of key)
    for (int id = t; id < SORT_N; id += 1024)
        sortbuf[id] = (id < cnt) ? ~g_cand[b * CAP + id] : ~0ull;
    __syncthreads();

    // bitonic sort, ascending on flipped key
    for (int k = 2; k <= SORT_N; k <<= 1) {
        for (int j = k >> 1; j > 0; j >>= 1) {
            for (int id = t; id < SORT_N; id += 1024) {
                int ixj = id ^ j;
                if (ixj > id) {
                    unsigned long long x = sortbuf[id], y = sortbuf[ixj];
                    bool up = ((id & k) == 0);
                    if ((x > y) == up) { sortbuf[id] = y; sortbuf[ixj] = x; }
                }
            }
            __syncthreads();
        }
    }

    unsigned long long key = ~sortbuf[t];   // element t of descending order
    __syncthreads();                        // done with sortbuf region

    bool  valid = (key != 0ull);
    float score = __uint_as_float((uint32_t)(key >> 32));
    uint32_t idx = 0xFFFFFFFFu - (uint32_t)key;

    float x1 = 0.f, y1 = 0.f, x2 = 0.f, y2 = 0.f, clsf = 0.f, off = 0.f;
    if (valid) {
        const float* pr = pred + ((size_t)b * NA + idx) * NC;
        float cx = pr[0], cy = pr[1], w = pr[2], h = pr[3];
        x1 = __fsub_rn(cx, __fmul_rn(w, 0.5f));
        y1 = __fsub_rn(cy, __fmul_rn(h, 0.5f));
        x2 = __fadd_rn(cx, __fmul_rn(w, 0.5f));
        y2 = __fadd_rn(cy, __fmul_rn(h, 0.5f));
        clsf = (float)g_cls[b * NA + idx];
        off  = __fmul_rn(clsf, MAXWH);
    }
    // offset boxes (replicates reference's fp32 rounding at magnitude cls*7680)
    float ox1 = __fadd_rn(x1, off), oy1 = __fadd_rn(y1, off);
    float ox2 = __fadd_rn(x2, off), oy2 = __fadd_rn(y2, off);
    if (!valid) { ox1 = oy1 = ox2 = oy2 = 0.f; }
    boxoff[t] = make_float4(ox1, oy1, ox2, oy2);
    area_s[t] = __fmul_rn(__fsub_rn(ox2, ox1), __fsub_rn(oy2, oy1));

    // zero suppression mask (transposed layout: conflict-free reads later)
    #pragma unroll
    for (int w = 0; w < 32; w++) maskC[w * 1024 + t] = 0u;
    __syncthreads();

    float myA = area_s[t];
    // balanced circular pairing: each unordered pair computed exactly once
    for (int d = 1; d <= 512; d++) {
        if (d == 512 && t >= 512) break;
        int j = (t + d) & 1023;
        float4 ob = boxoff[j];
        float ltx = fmaxf(ox1, ob.x), lty = fmaxf(oy1, ob.y);
        float rbx = fminf(ox2, ob.z), rby = fminf(oy2, ob.w);
        float ww = fmaxf(__fsub_rn(rbx, ltx), 0.0f);
        float hh = fmaxf(__fsub_rn(rby, lty), 0.0f);
        float inter = __fmul_rn(ww, hh);
        float uni   = __fadd_rn(__fsub_rn(__fadd_rn(myA, area_s[j]), inter), 1e-7f);
        float iou   = __fdiv_rn(inter, uni);
        if (iou > IOU_T) {
            int lo = (t < j) ? t : j;
            int hi = (t < j) ? j : t;
            atomicOr(&maskC[(lo >> 5) * 1024 + hi], 1u << (lo & 31));
        }
    }

    // keep init = valid
    {
        unsigned bal = __ballot_sync(0xffffffffu, valid);
        if ((t & 31) == 0) keep_s[t >> 5] = bal;
    }
    __syncthreads();

    // Jacobi fixed-point of greedy NMS: keep[i] = valid[i] & !any(kept j<i suppressing i)
    for (int it = 0; it < SORT_N; it++) {
        uint32_t acc = 0;
        #pragma unroll
        for (int w = 0; w < 32; w++) acc |= maskC[w * 1024 + t] & keep_s[w];
        int nb  = (valid && acc == 0) ? 1 : 0;
        int old = (keep_s[t >> 5] >> (t & 31)) & 1;
        __syncthreads();
        unsigned nbal = __ballot_sync(0xffffffffu, nb);
        if ((t & 31) == 0) keep_s[t >> 5] = nbal;
        int changed = __syncthreads_or(nb != old);
        if (!changed) break;
    }

    // rank kept items (already in descending-score order) and emit top-100
    if (t == 0) {
        pfx[0] = 0;
        for (int w = 0; w < 32; w++) pfx[w + 1] = pfx[w] + __popc(keep_s[w]);
    }
    __syncthreads();

    uint32_t kw = keep_s[t >> 5];
    if (valid && ((kw >> (t & 31)) & 1)) {
        int rank = pfx[t >> 5] + __popc(kw & ((1u << (t & 31)) - 1u));
        if (rank < MAX_DET) {
            float* o = out + ((size_t)b * MAX_DET + rank) * 6;
            o[0] = x1; o[1] = y1; o[2] = x2; o[3] = y2;
            o[4] = score; o[5] = clsf;
        }
    }
}

// ---------------- launcher ----------------
extern "C" void kernel_launch(void* const* d_in, const int* in_sizes, int n_in,
                              void* d_out, int out_size) {
    (void)in_sizes; (void)n_in; (void)out_size;
    const float* pred = (const float*)d_in[0];
    float* out = (float*)d_out;

    cudaFuncSetAttribute(nms_kernel, cudaFuncAttributeMaxDynamicSharedMemorySize, 147456);

    zero_kernel  <<<(B * NBINS + 255) / 256, 256>>>();
    score_kernel <<<(B * NA + 7) / 8, 256>>>(pred);
    thresh_kernel<<<B, 32>>>();
    gather_kernel<<<(B * NA + 255) / 256, 256>>>();
    nms_kernel   <<<B, 1024, 147456>>>(pred, out);
}

// round 2
// speedup vs baseline: 1.8475x; 1.8475x over previous
#include <cuda_runtime.h>
#include <cstdint>

#define B       8
#define NA      100800
#define NC      85
#define K_PRE   1024
#define MAX_DET 100
#define NBINS   8192
#define CAP     2048
#define SORT_N  2048
#define CONF    0.25f
#define IOU_T   0.45f
#define MAXWH   7680.0f

// ---------------- device scratch (no allocations allowed) ----------------
__device__ uint32_t           g_keys[B * NA];
__device__ uint8_t            g_cls [B * NA];
__device__ uint32_t           g_hist[B * NBINS];
__device__ int                g_T   [B];
__device__ int                g_cnt [B];
__device__ unsigned long long g_cand[B * CAP];
// sorted per-batch candidate data
__device__ float4             g_bx  [B * K_PRE];   // class-offset boxes
__device__ float              g_area[B * K_PRE];
__device__ float4             g_raw [B * K_PRE];   // un-offset boxes (output)
__device__ float2             g_sc  [B * K_PRE];   // (score, cls)
// suppression bitmask, transposed: word w of row i at [(b*32+w)*1024 + i]
__device__ uint32_t           g_maskT[B * 32 * K_PRE];

// ---------------- kernel 0: zero histogram + counters ----------------
__global__ void zero_kernel() {
    int i = blockIdx.x * blockDim.x + threadIdx.x;
    if (i < B * NBINS) g_hist[i] = 0u;
    if (i < B)         g_cnt[i]  = 0;
}

// ---------------- kernel 1: per-anchor score / cls (warp per anchor) ----------------
__global__ void score_kernel(const float* __restrict__ pred) {
    int warp = (blockIdx.x * blockDim.x + threadIdx.x) >> 5;
    int lane = threadIdx.x & 31;
    if (warp >= B * NA) return;

    const float* p = pred + (size_t)warp * NC;
    float v1 = p[lane];                              // idx 0..31
    float v2 = p[32 + lane];                         // idx 32..63
    float v3 = (lane < 21) ? p[64 + lane] : 0.0f;    // idx 64..84

    const unsigned F = 0xffffffffu;
    float obj = __shfl_sync(F, v1, 4);

    float best = -1.0f; int bid = 0;
    if (lane >= 5) { best = __fmul_rn(v1, obj); bid = lane - 5; }
    {
        float c2 = __fmul_rn(v2, obj);
        if (c2 > best) { best = c2; bid = lane + 27; }
    }
    if (lane < 21) {
        float c3 = __fmul_rn(v3, obj);
        if (c3 > best) { best = c3; bid = lane + 59; }
    }
    for (int o = 16; o; o >>= 1) {
        float ov = __shfl_xor_sync(F, best, o);
        int   oi = __shfl_xor_sync(F, bid,  o);
        if (ov > best || (ov == best && oi < bid)) { best = ov; bid = oi; }
    }

    if (lane == 0) {
        bool valid = (obj > CONF) && (best > CONF);
        g_keys[warp] = valid ? __float_as_uint(best) : 0u;
        g_cls [warp] = (uint8_t)bid;
        if (valid) {
            int b = warp / NA;
            int bin = (int)(best * (float)NBINS);
            if (bin > NBINS - 1) bin = NBINS - 1;
            atomicAdd(&g_hist[b * NBINS + bin], 1u);
        }
    }
}

// ---------------- kernel 2: per-batch threshold bin (top-K cutoff) ----------------
__global__ void thresh_kernel() {
    int b = blockIdx.x;
    int lane = threadIdx.x;
    const unsigned F = 0xffffffffu;
    int acc = 0;
    int T = 0;
    for (int hi = NBINS - 1; hi >= 31; hi -= 32) {
        int c = (int)g_hist[b * NBINS + hi - lane];
        int ps = c;
        for (int o = 1; o < 32; o <<= 1) {
            int v = __shfl_up_sync(F, ps, o);
            if (lane >= o) ps += v;
        }
        int tot = __shfl_sync(F, ps, 31);
        unsigned bal = __ballot_sync(F, acc + ps >= K_PRE);
        if (bal) { int l = __ffs(bal) - 1; T = hi - l; break; }
        acc += tot;
    }
    if (lane == 0) g_T[b] = T;
}

// ---------------- kernel 3: gather candidates >= threshold (4 keys/thread) ----------------
__global__ void gather_kernel() {
    int base = (blockIdx.x * blockDim.x + threadIdx.x) * 4;
    if (base >= B * NA) return;
    uint4 k4 = *(const uint4*)(g_keys + base);     // NA % 4 == 0 -> no batch crossing
    int b = base / NA;
    int T = g_T[b];
    uint32_t ks[4] = {k4.x, k4.y, k4.z, k4.w};
    #pragma unroll
    for (int u = 0; u < 4; u++) {
        uint32_t key = ks[u];
        if (!key) continue;
        float s = __uint_as_float(key);
        int bin = (int)(s * (float)NBINS);
        if (bin > NBINS - 1) bin = NBINS - 1;
        if (bin < T) continue;
        int pos = atomicAdd(&g_cnt[b], 1);
        if (pos < CAP) {
            uint32_t li = (uint32_t)(base + u - b * NA);
            g_cand[b * CAP + pos] =
                ((unsigned long long)key << 32) | (unsigned long long)(0xFFFFFFFFu - li);
        }
    }
}

// ---------------- kernel 4: bitonic sort + box precompute (one block/batch) ----------------
__global__ void __launch_bounds__(1024, 1)
sort_kernel(const float* __restrict__ pred) {
    __shared__ unsigned long long sb[SORT_N];
    int b = blockIdx.x;
    int t = threadIdx.x;

    int cnt = g_cnt[b];
    if (cnt > CAP) cnt = CAP;
    for (int id = t; id < SORT_N; id += 1024)
        sb[id] = (id < cnt) ? ~g_cand[b * CAP + id] : ~0ull;
    __syncthreads();

    // bitonic sort ascending on flipped key == descending on (score, -idx)
    for (int k = 2; k <= SORT_N; k <<= 1) {
        for (int j = k >> 1; j > 0; j >>= 1) {
            for (int id = t; id < SORT_N; id += 1024) {
                int ixj = id ^ j;
                if (ixj > id) {
                    unsigned long long x = sb[id], y = sb[ixj];
                    bool up = ((id & k) == 0);
                    if ((x > y) == up) { sb[id] = y; sb[ixj] = x; }
                }
            }
            __syncthreads();
        }
    }

    unsigned long long key = ~sb[t];   // element t of descending order (top 1024)
    bool  valid = (key != 0ull);
    float score = __uint_as_float((uint32_t)(key >> 32));
    uint32_t idx = 0xFFFFFFFFu - (uint32_t)key;

    float x1 = 0.f, y1 = 0.f, x2 = 0.f, y2 = 0.f, clsf = 0.f, off = 0.f;
    if (valid) {
        const float* pr = pred + ((size_t)b * NA + idx) * NC;
        float cx = pr[0], cy = pr[1], w = pr[2], h = pr[3];
        x1 = __fsub_rn(cx, __fmul_rn(w, 0.5f));
        y1 = __fsub_rn(cy, __fmul_rn(h, 0.5f));
        x2 = __fadd_rn(cx, __fmul_rn(w, 0.5f));
        y2 = __fadd_rn(cy, __fmul_rn(h, 0.5f));
        clsf = (float)g_cls[b * NA + idx];
        off  = __fmul_rn(clsf, MAXWH);
    } else {
        score = 0.f;
    }
    float ox1 = __fadd_rn(x1, off), oy1 = __fadd_rn(y1, off);
    float ox2 = __fadd_rn(x2, off), oy2 = __fadd_rn(y2, off);
    if (!valid) { ox1 = oy1 = ox2 = oy2 = 0.f; }

    g_bx  [b * K_PRE + t] = make_float4(ox1, oy1, ox2, oy2);
    g_area[b * K_PRE + t] = __fmul_rn(__fsub_rn(ox2, ox1), __fsub_rn(oy2, oy1));
    g_raw [b * K_PRE + t] = make_float4(x1, y1, x2, y2);
    g_sc  [b * K_PRE + t] = make_float2(score, clsf);
}

// ---------------- kernel 5: full-chip suppression mask (64x64 tiles) ----------------
__global__ void mask_kernel() {
    int jt = blockIdx.x;   // suppressor tile (cols)
    int it = blockIdx.y;   // suppressee tile (rows)
    int b  = blockIdx.z;
    int t  = threadIdx.x;  // 64 threads: one row each
    int i  = it * 64 + t;

    uint32_t w0 = 0u, w1 = 0u;
    if (jt <= it) {
        __shared__ float4 jb[64];
        __shared__ float  ja[64];
        jb[t] = g_bx  [b * K_PRE + jt * 64 + t];
        ja[t] = g_area[b * K_PRE + jt * 64 + t];
        __syncthreads();

        float4 ib = g_bx  [b * K_PRE + i];
        float  ia = g_area[b * K_PRE + i];

        #pragma unroll 8
        for (int jj = 0; jj < 64; jj++) {
            int j = jt * 64 + jj;
            if (j >= i) break;                 // only higher-score (lower index) suppresses
            float4 ob = jb[jj];
            float ltx = fmaxf(ib.x, ob.x), lty = fmaxf(ib.y, ob.y);
            float rbx = fminf(ib.z, ob.z), rby = fminf(ib.w, ob.w);
            float ww = fmaxf(__fsub_rn(rbx, ltx), 0.0f);
            float hh = fmaxf(__fsub_rn(rby, lty), 0.0f);
            float inter = __fmul_rn(ww, hh);
            float uni   = __fadd_rn(__fsub_rn(__fadd_rn(ia, ja[jj]), inter), 1e-7f);
            float iou   = __fdiv_rn(inter, uni);
            if (iou > IOU_T) {
                if (jj < 32) w0 |= 1u << jj;
                else         w1 |= 1u << (jj - 32);
            }
        }
    }
    g_maskT[(b * 32 + jt * 2 + 0) * K_PRE + i] = w0;
    g_maskT[(b * 32 + jt * 2 + 1) * K_PRE + i] = w1;
}

// ---------------- kernel 6: Jacobi greedy-NMS resolution + output ----------------
__global__ void __launch_bounds__(1024, 1)
final_kernel(float* __restrict__ out) {
    int b = blockIdx.x;
    int t = threadIdx.x;

    __shared__ uint32_t keep_s[32];
    __shared__ int      pfx[33];

    if (t < MAX_DET * 6) out[b * MAX_DET * 6 + t] = 0.0f;

    float2 sc = g_sc[b * K_PRE + t];
    bool valid = sc.x > 0.0f;

    uint32_t row[32];
    #pragma unroll
    for (int w = 0; w < 32; w++) row[w] = g_maskT[(b * 32 + w) * K_PRE + t];

    {
        unsigned bal = __ballot_sync(0xffffffffu, valid);
        if ((t & 31) == 0) keep_s[t >> 5] = bal;
    }
    __syncthreads();

    // Jacobi fixed-point: keep[i] = valid[i] & !any(kept j<i suppressing i)
    for (int it = 0; it < K_PRE; it++) {
        uint32_t acc = 0;
        #pragma unroll
        for (int w = 0; w < 32; w++) acc |= row[w] & keep_s[w];
        int nb  = (valid && acc == 0) ? 1 : 0;
        int old = (keep_s[t >> 5] >> (t & 31)) & 1;
        __syncthreads();
        unsigned nbal = __ballot_sync(0xffffffffu, nb);
        if ((t & 31) == 0) keep_s[t >> 5] = nbal;
        int changed = __syncthreads_or(nb != old);
        if (!changed) break;
    }

    if (t == 0) {
        pfx[0] = 0;
        for (int w = 0; w < 32; w++) pfx[w + 1] = pfx[w] + __popc(keep_s[w]);
    }
    __syncthreads();

    uint32_t kw = keep_s[t >> 5];
    if (valid && ((kw >> (t & 31)) & 1)) {
        int rank = pfx[t >> 5] + __popc(kw & ((1u << (t & 31)) - 1u));
        if (rank < MAX_DET) {
            float4 r = g_raw[b * K_PRE + t];
            float* o = out + ((size_t)b * MAX_DET + rank) * 6;
            o[0] = r.x; o[1] = r.y; o[2] = r.z; o[3] = r.w;
            o[4] = sc.x; o[5] = sc.y;
        }
    }
}

// ---------------- launcher ----------------
extern "C" void kernel_launch(void* const* d_in, const int* in_sizes, int n_in,
                              void* d_out, int out_size) {
    (void)in_sizes; (void)n_in; (void)out_size;
    const float* pred = (const float*)d_in[0];
    float* out = (float*)d_out;

    zero_kernel  <<<(B * NBINS + 255) / 256, 256>>>();
    score_kernel <<<(B * NA + 7) / 8, 256>>>(pred);
    thresh_kernel<<<B, 32>>>();
    gather_kernel<<<(B * NA / 4 + 255) / 256, 256>>>();
    sort_kernel  <<<B, 1024>>>(pred);
    mask_kernel  <<<dim3(16, 16, B), 64>>>();
    final_kernel <<<B, 1024>>>(out);
}

// round 3
// speedup vs baseline: 2.2047x; 1.1934x over previous
#include <cuda_runtime.h>
#include <cstdint>

#define B       8
#define NA      100800
#define NC      85
#define K_PRE   1024
#define MAX_DET 100
#define NBINS   8192
#define CAP     2048
#define SORT_N  2048
#define CONF    0.25f
#define IOU_T   0.45f
#define MAXWH   7680.0f

// ---------------- device scratch (no allocations allowed) ----------------
__device__ uint32_t           g_keys[B * NA];
__device__ uint8_t            g_cls [B * NA];
__device__ uint32_t           g_hist[B * NBINS];
__device__ int                g_T   [B];
__device__ int                g_cnt [B];
__device__ unsigned long long g_cand[B * CAP];
// sorted per-batch candidate data
__device__ float4             g_bx  [B * K_PRE];   // class-offset boxes
__device__ float              g_area[B * K_PRE];
__device__ float4             g_raw [B * K_PRE];   // un-offset boxes (output)
__device__ float2             g_sc  [B * K_PRE];   // (score, cls)
// suppression bitmask, transposed: word w of row i at [(b*32+w)*1024 + i]
__device__ uint32_t           g_maskT[B * 32 * K_PRE];

// ---------------- kernel 0: zero histogram + counters ----------------
__global__ void zero_kernel() {
    int i = blockIdx.x * blockDim.x + threadIdx.x;
    if (i < B * NBINS) g_hist[i] = 0u;
    if (i < B)         g_cnt[i]  = 0;
}

// ---------------- kernel 1: per-anchor score / cls (warp per anchor) ----------------
__global__ void score_kernel(const float* __restrict__ pred) {
    int warp = (blockIdx.x * blockDim.x + threadIdx.x) >> 5;
    int lane = threadIdx.x & 31;
    if (warp >= B * NA) return;

    const float* p = pred + (size_t)warp * NC;
    float v1 = __ldcs(p + lane);                               // idx 0..31
    float v2 = __ldcs(p + 32 + lane);                          // idx 32..63
    float v3 = (lane < 21) ? __ldcs(p + 64 + lane) : 0.0f;     // idx 64..84

    const unsigned F = 0xffffffffu;
    float obj = __shfl_sync(F, v1, 4);

    // per-lane best product with min-class tie-break (classes ascend per lane)
    float best = -1.0f; unsigned bid = 0xFFu;
    if (lane >= 5) { best = __fmul_rn(v1, obj); bid = lane - 5; }
    {
        float c2 = __fmul_rn(v2, obj);
        if (c2 > best) { best = c2; bid = lane + 27; }
    }
    if (lane < 21) {
        float c3 = __fmul_rn(v3, obj);
        if (c3 > best) { best = c3; bid = lane + 59; }
    }
    // every lane's best is >= 0 here -> float bits are order-monotonic
    unsigned bbits = __float_as_uint(best);
    unsigned vmax  = __reduce_max_sync(F, bbits);
    unsigned cand  = (bbits == vmax) ? bid : 0xFFu;
    unsigned bmin  = __reduce_min_sync(F, cand);   // JAX argmax: lowest class wins ties

    if (lane == 0) {
        float score = __uint_as_float(vmax);
        bool valid = (obj > CONF) && (score > CONF);
        g_keys[warp] = valid ? vmax : 0u;
        g_cls [warp] = (uint8_t)bmin;
        if (valid) {
            int b = warp / NA;
            int bin = (int)(score * (float)NBINS);
            if (bin > NBINS - 1) bin = NBINS - 1;
            atomicAdd(&g_hist[b * NBINS + bin], 1u);
        }
    }
}

// ---------------- kernel 2: per-batch threshold bin (top-K cutoff) ----------------
__global__ void thresh_kernel() {
    int b = blockIdx.x;
    int lane = threadIdx.x;
    const unsigned F = 0xffffffffu;
    int acc = 0;
    int T = 0;
    for (int hi = NBINS - 1; hi >= 31; hi -= 32) {
        int c = (int)g_hist[b * NBINS + hi - lane];
        int ps = c;
        for (int o = 1; o < 32; o <<= 1) {
            int v = __shfl_up_sync(F, ps, o);
            if (lane >= o) ps += v;
        }
        int tot = __shfl_sync(F, ps, 31);
        unsigned bal = __ballot_sync(F, acc + ps >= K_PRE);
        if (bal) { int l = __ffs(bal) - 1; T = hi - l; break; }
        acc += tot;
    }
    if (lane == 0) g_T[b] = T;
}

// ---------------- kernel 3: gather (block-aggregated atomics) ----------------
__global__ void gather_kernel() {
    __shared__ int s_cnt, s_base;
    int b = blockIdx.y;
    int base = (blockIdx.x * blockDim.x + threadIdx.x) * 4;  // anchor idx within batch
    if (threadIdx.x == 0) s_cnt = 0;
    __syncthreads();

    uint32_t ks[4] = {0u, 0u, 0u, 0u};
    int pos[4];
    bool pass[4] = {false, false, false, false};

    if (base < NA) {   // NA % 4 == 0 -> full vector or nothing
        uint4 k4 = *(const uint4*)(g_keys + (size_t)b * NA + base);
        ks[0] = k4.x; ks[1] = k4.y; ks[2] = k4.z; ks[3] = k4.w;
        int T = g_T[b];
        #pragma unroll
        for (int u = 0; u < 4; u++) {
            uint32_t key = ks[u];
            if (!key) continue;
            float s = __uint_as_float(key);
            int bin = (int)(s * (float)NBINS);
            if (bin > NBINS - 1) bin = NBINS - 1;
            if (bin < T) continue;
            pos[u] = atomicAdd(&s_cnt, 1);   // smem atomic, cheap
            pass[u] = true;
        }
    }
    __syncthreads();
    if (threadIdx.x == 0) s_base = (s_cnt > 0) ? atomicAdd(&g_cnt[b], s_cnt) : 0;
    __syncthreads();

    #pragma unroll
    for (int u = 0; u < 4; u++) {
        if (pass[u]) {
            int p = s_base + pos[u];
            if (p < CAP) {
                uint32_t li = (uint32_t)(base + u);
                g_cand[b * CAP + p] =
                    ((unsigned long long)ks[u] << 32) |
                    (unsigned long long)(0xFFFFFFFFu - li);
            }
        }
    }
}

// ---------------- kernel 4: bitonic sort + box precompute (one block/batch) ----------------
__global__ void __launch_bounds__(1024, 1)
sort_kernel(const float* __restrict__ pred) {
    __shared__ unsigned long long sb[SORT_N];
    int b = blockIdx.x;
    int t = threadIdx.x;

    int cnt = g_cnt[b];
    if (cnt > CAP) cnt = CAP;
    for (int id = t; id < SORT_N; id += 1024)
        sb[id] = (id < cnt) ? ~g_cand[b * CAP + id] : ~0ull;
    __syncthreads();

    // bitonic sort ascending on flipped key == descending on (score, -idx)
    for (int k = 2; k <= SORT_N; k <<= 1) {
        for (int j = k >> 1; j > 0; j >>= 1) {
            for (int id = t; id < SORT_N; id += 1024) {
                int ixj = id ^ j;
                if (ixj > id) {
                    unsigned long long x = sb[id], y = sb[ixj];
                    bool up = ((id & k) == 0);
                    if ((x > y) == up) { sb[id] = y; sb[ixj] = x; }
                }
            }
            __syncthreads();
        }
    }

    unsigned long long key = ~sb[t];   // element t of descending order (top 1024)
    bool  valid = (key != 0ull);
    float score = __uint_as_float((uint32_t)(key >> 32));
    uint32_t idx = 0xFFFFFFFFu - (uint32_t)key;

    float x1 = 0.f, y1 = 0.f, x2 = 0.f, y2 = 0.f, clsf = 0.f, off = 0.f;
    if (valid) {
        const float* pr = pred + ((size_t)b * NA + idx) * NC;
        float cx = pr[0], cy = pr[1], w = pr[2], h = pr[3];
        x1 = __fsub_rn(cx, __fmul_rn(w, 0.5f));
        y1 = __fsub_rn(cy, __fmul_rn(h, 0.5f));
        x2 = __fadd_rn(cx, __fmul_rn(w, 0.5f));
        y2 = __fadd_rn(cy, __fmul_rn(h, 0.5f));
        clsf = (float)g_cls[b * NA + idx];
        off  = __fmul_rn(clsf, MAXWH);
    } else {
        score = 0.f;
    }
    float ox1 = __fadd_rn(x1, off), oy1 = __fadd_rn(y1, off);
    float ox2 = __fadd_rn(x2, off), oy2 = __fadd_rn(y2, off);
    if (!valid) { ox1 = oy1 = ox2 = oy2 = 0.f; }

    g_bx  [b * K_PRE + t] = make_float4(ox1, oy1, ox2, oy2);
    g_area[b * K_PRE + t] = __fmul_rn(__fsub_rn(ox2, ox1), __fsub_rn(oy2, oy1));
    g_raw [b * K_PRE + t] = make_float4(x1, y1, x2, y2);
    g_sc  [b * K_PRE + t] = make_float2(score, clsf);
}

// ---------------- kernel 5: full-chip suppression mask (64x64 tiles) ----------------
__global__ void mask_kernel() {
    int jt = blockIdx.x;   // suppressor tile (cols)
    int it = blockIdx.y;   // suppressee tile (rows)
    int b  = blockIdx.z;
    int t  = threadIdx.x;  // 64 threads: one row each
    int i  = it * 64 + t;

    uint32_t w0 = 0u, w1 = 0u;
    if (jt <= it) {
        __shared__ float4 jb[64];
        __shared__ float  ja[64];
        jb[t] = g_bx  [b * K_PRE + jt * 64 + t];
        ja[t] = g_area[b * K_PRE + jt * 64 + t];
        __syncthreads();

        float4 ib = g_bx  [b * K_PRE + i];
        float  ia = g_area[b * K_PRE + i];

        #pragma unroll 8
        for (int jj = 0; jj < 64; jj++) {
            int j = jt * 64 + jj;
            if (j >= i) break;                 // only higher-score (lower index) suppresses
            float4 ob = jb[jj];
            float ltx = fmaxf(ib.x, ob.x), lty = fmaxf(ib.y, ob.y);
            float rbx = fminf(ib.z, ob.z), rby = fminf(ib.w, ob.w);
            float ww = fmaxf(__fsub_rn(rbx, ltx), 0.0f);
            float hh = fmaxf(__fsub_rn(rby, lty), 0.0f);
            float inter = __fmul_rn(ww, hh);
            float uni   = __fadd_rn(__fsub_rn(__fadd_rn(ia, ja[jj]), inter), 1e-7f);
            float iou   = __fdiv_rn(inter, uni);
            if (iou > IOU_T) {
                if (jj < 32) w0 |= 1u << jj;
                else         w1 |= 1u << (jj - 32);
            }
        }
    }
    g_maskT[(b * 32 + jt * 2 + 0) * K_PRE + i] = w0;
    g_maskT[(b * 32 + jt * 2 + 1) * K_PRE + i] = w1;
}

// ---------------- kernel 6: Jacobi greedy-NMS resolution + output ----------------
__global__ void __launch_bounds__(1024, 1)
final_kernel(float* __restrict__ out) {
    int b = blockIdx.x;
    int t = threadIdx.x;

    __shared__ uint32_t keep_s[32];
    __shared__ int      pfx[33];

    if (t < MAX_DET * 6) out[b * MAX_DET * 6 + t] = 0.0f;

    float2 sc = g_sc[b * K_PRE + t];
    bool valid = sc.x > 0.0f;

    uint32_t row[32];
    #pragma unroll
    for (int w = 0; w < 32; w++) row[w] = g_maskT[(b * 32 + w) * K_PRE + t];

    {
        unsigned bal = __ballot_sync(0xffffffffu, valid);
        if ((t & 31) == 0) keep_s[t >> 5] = bal;
    }
    __syncthreads();

    // Jacobi fixed-point: keep[i] = valid[i] & !any(kept j<i suppressing i)
    for (int it = 0; it < K_PRE; it++) {
        uint32_t acc = 0;
        #pragma unroll
        for (int w = 0; w < 32; w++) acc |= row[w] & keep_s[w];
        int nb  = (valid && acc == 0) ? 1 : 0;
        int old = (keep_s[t >> 5] >> (t & 31)) & 1;
        __syncthreads();
        unsigned nbal = __ballot_sync(0xffffffffu, nb);
        if ((t & 31) == 0) keep_s[t >> 5] = nbal;
        int changed = __syncthreads_or(nb != old);
        if (!changed) break;
    }

    if (t == 0) {
        pfx[0] = 0;
        for (int w = 0; w < 32; w++) pfx[w + 1] = pfx[w] + __popc(keep_s[w]);
    }
    __syncthreads();

    uint32_t kw = keep_s[t >> 5];
    if (valid && ((kw >> (t & 31)) & 1)) {
        int rank = pfx[t >> 5] + __popc(kw & ((1u << (t & 31)) - 1u));
        if (rank < MAX_DET) {
            float4 r = g_raw[b * K_PRE + t];
            float* o = out + ((size_t)b * MAX_DET + rank) * 6;
            o[0] = r.x; o[1] = r.y; o[2] = r.z; o[3] = r.w;
            o[4] = sc.x; o[5] = sc.y;
        }
    }
}

// ---------------- launcher ----------------
extern "C" void kernel_launch(void* const* d_in, const int* in_sizes, int n_in,
                              void* d_out, int out_size) {
    (void)in_sizes; (void)n_in; (void)out_size;
    const float* pred = (const float*)d_in[0];
    float* out = (float*)d_out;

    zero_kernel  <<<(B * NBINS + 255) / 256, 256>>>();
    score_kernel <<<(B * NA + 7) / 8, 256>>>(pred);
    thresh_kernel<<<B, 32>>>();
    gather_kernel<<<dim3((NA / 4 + 255) / 256, B), 256>>>();
    sort_kernel  <<<B, 1024>>>(pred);
    mask_kernel  <<<dim3(16, 16, B), 64>>>();
    final_kernel <<<B, 1024>>>(out);
}

// round 4
// speedup vs baseline: 2.6353x; 1.1953x over previous
#include <cuda_runtime.h>
#include <cstdint>

#define B       8
#define NA      100800
#define NC      85
#define K_PRE   1024
#define MAX_DET 100
#define NBINS   8192
#define CAP     2048
#define SORT_N  2048
#define CONF    0.25f
#define IOU_T   0.45f
#define MAXWH   7680.0f
#define G_ANCH  32                       // anchors per score block

// ---------------- device scratch (no allocations allowed) ----------------
__device__ uint32_t           g_keys[B * NA];
__device__ uint8_t            g_cls [B * NA];
__device__ uint32_t           g_hist[B * NBINS];
__device__ int                g_T   [B];
__device__ int                g_cnt [B];
__device__ unsigned long long g_cand[B * CAP];
__device__ float4             g_bx  [B * K_PRE];   // class-offset boxes
__device__ float              g_area[B * K_PRE];
__device__ float4             g_raw [B * K_PRE];   // un-offset boxes (output)
__device__ float2             g_sc  [B * K_PRE];   // (score, cls)
// suppression bitmask, transposed: word w of row i at [(b*32+w)*1024 + i]
__device__ uint32_t           g_maskT[B * 32 * K_PRE];

// ---------------- kernel 0: zero histogram + counters ----------------
__global__ void zero_kernel() {
    int i = blockIdx.x * blockDim.x + threadIdx.x;
    if (i < B * NBINS) g_hist[i] = 0u;
    if (i < B)         g_cnt[i]  = 0;
}

// ---------------- kernel 1: score/cls — float4 staged via smem ----------------
__global__ void __launch_bounds__(256)
score_kernel(const float* __restrict__ pred) {
    __shared__ float sb[G_ANCH * NC];          // 2720 floats = 10880 B
    int blk = blockIdx.x;                      // 25200 blocks; 32|NA -> no batch straddle
    int t   = threadIdx.x;

    // stage 32 anchors with perfectly-coalesced float4 loads (base 16B-aligned)
    const float4* src = (const float4*)(pred + (size_t)blk * (G_ANCH * NC));
    float4* dst = (float4*)sb;
    #pragma unroll
    for (int r = 0; r < 3; r++) {
        int i = r * 256 + t;
        if (i < (G_ANCH * NC) / 4) dst[i] = __ldcs(src + i);
    }
    __syncthreads();

    int wid = t >> 5, lane = t & 31;
    const unsigned F = 0xffffffffu;

    #pragma unroll
    for (int u = 0; u < 4; u++) {
        int a = wid * 4 + u;                   // 0..31 within block
        const float* p = sb + a * NC;
        float v1 = p[lane];                              // idx 0..31
        float v2 = p[32 + lane];                         // idx 32..63
        float v3 = (lane < 21) ? p[64 + lane] : 0.0f;    // idx 64..84

        float obj = __shfl_sync(F, v1, 4);

        float best = -1.0f; unsigned bid = 0xFFu;
        if (lane >= 5) { best = __fmul_rn(v1, obj); bid = lane - 5; }
        {
            float c2 = __fmul_rn(v2, obj);
            if (c2 > best) { best = c2; bid = lane + 27; }
        }
        if (lane < 21) {
            float c3 = __fmul_rn(v3, obj);
            if (c3 > best) { best = c3; bid = lane + 59; }
        }
        // all bests >= 0 -> float bits order-monotonic
        unsigned bbits = __float_as_uint(best);
        unsigned vmax  = __reduce_max_sync(F, bbits);
        unsigned cand  = (bbits == vmax) ? bid : 0xFFu;
        unsigned bmin  = __reduce_min_sync(F, cand);   // lowest class wins ties

        if (lane == 0) {
            int anchor = blk * G_ANCH + a;
            float score = __uint_as_float(vmax);
            bool valid = (obj > CONF) && (score > CONF);
            g_keys[anchor] = valid ? vmax : 0u;
            g_cls [anchor] = (uint8_t)bmin;
            if (valid) {
                int b = anchor / NA;
                int bin = (int)(score * (float)NBINS);
                if (bin > NBINS - 1) bin = NBINS - 1;
                atomicAdd(&g_hist[b * NBINS + bin], 1u);
            }
        }
    }
}

// ---------------- kernel 2: per-batch threshold bin (top-K cutoff) ----------------
__global__ void thresh_kernel() {
    int b = blockIdx.x;
    int lane = threadIdx.x;
    const unsigned F = 0xffffffffu;
    int acc = 0;
    int T = 0;
    for (int hi = NBINS - 1; hi >= 31; hi -= 32) {
        int c = (int)g_hist[b * NBINS + hi - lane];
        int ps = c;
        for (int o = 1; o < 32; o <<= 1) {
            int v = __shfl_up_sync(F, ps, o);
            if (lane >= o) ps += v;
        }
        int tot = __shfl_sync(F, ps, 31);
        unsigned bal = __ballot_sync(F, acc + ps >= K_PRE);
        if (bal) { int l = __ffs(bal) - 1; T = hi - l; break; }
        acc += tot;
    }
    if (lane == 0) g_T[b] = T;
}

// ---------------- kernel 3: gather (block-aggregated atomics, 8 keys/thread) ----------------
__global__ void gather_kernel() {
    __shared__ int s_cnt, s_base;
    int b = blockIdx.y;
    int base = (blockIdx.x * blockDim.x + threadIdx.x) * 8;  // anchor idx within batch
    if (threadIdx.x == 0) s_cnt = 0;
    __syncthreads();

    uint32_t ks[8];
    int pos[8];
    bool pass[8] = {false,false,false,false,false,false,false,false};

    if (base < NA) {   // NA % 8 == 0 -> full vector or nothing
        const uint4* kp = (const uint4*)(g_keys + (size_t)b * NA + base);
        uint4 k0 = kp[0], k1 = kp[1];
        ks[0]=k0.x; ks[1]=k0.y; ks[2]=k0.z; ks[3]=k0.w;
        ks[4]=k1.x; ks[5]=k1.y; ks[6]=k1.z; ks[7]=k1.w;
        int T = g_T[b];
        #pragma unroll
        for (int u = 0; u < 8; u++) {
            uint32_t key = ks[u];
            if (!key) continue;
            float s = __uint_as_float(key);
            int bin = (int)(s * (float)NBINS);
            if (bin > NBINS - 1) bin = NBINS - 1;
            if (bin < T) continue;
            pos[u] = atomicAdd(&s_cnt, 1);
            pass[u] = true;
        }
    }
    __syncthreads();
    if (threadIdx.x == 0) s_base = (s_cnt > 0) ? atomicAdd(&g_cnt[b], s_cnt) : 0;
    __syncthreads();

    #pragma unroll
    for (int u = 0; u < 8; u++) {
        if (pass[u]) {
            int p = s_base + pos[u];
            if (p < CAP) {
                uint32_t li = (uint32_t)(base + u);
                g_cand[b * CAP + p] =
                    ((unsigned long long)ks[u] << 32) |
                    (unsigned long long)(0xFFFFFFFFu - li);
            }
        }
    }
}

// ---------------- kernel 4: bitonic sort + box precompute (one block/batch) ----------------
__global__ void __launch_bounds__(1024, 1)
sort_kernel(const float* __restrict__ pred) {
    __shared__ unsigned long long sb[SORT_N];
    int b = blockIdx.x;
    int t = threadIdx.x;

    int cnt = g_cnt[b];
    if (cnt > CAP) cnt = CAP;
    for (int id = t; id < SORT_N; id += 1024)
        sb[id] = (id < cnt) ? ~g_cand[b * CAP + id] : ~0ull;
    __syncthreads();

    for (int k = 2; k <= SORT_N; k <<= 1) {
        for (int j = k >> 1; j > 0; j >>= 1) {
            for (int id = t; id < SORT_N; id += 1024) {
                int ixj = id ^ j;
                if (ixj > id) {
                    unsigned long long x = sb[id], y = sb[ixj];
                    bool up = ((id & k) == 0);
                    if ((x > y) == up) { sb[id] = y; sb[ixj] = x; }
                }
            }
            __syncthreads();
        }
    }

    unsigned long long key = ~sb[t];   // element t of descending order (top 1024)
    bool  valid = (key != 0ull);
    float score = __uint_as_float((uint32_t)(key >> 32));
    uint32_t idx = 0xFFFFFFFFu - (uint32_t)key;

    float x1 = 0.f, y1 = 0.f, x2 = 0.f, y2 = 0.f, clsf = 0.f, off = 0.f;
    if (valid) {
        const float* pr = pred + ((size_t)b * NA + idx) * NC;
        float cx = pr[0], cy = pr[1], w = pr[2], h = pr[3];
        x1 = __fsub_rn(cx, __fmul_rn(w, 0.5f));
        y1 = __fsub_rn(cy, __fmul_rn(h, 0.5f));
        x2 = __fadd_rn(cx, __fmul_rn(w, 0.5f));
        y2 = __fadd_rn(cy, __fmul_rn(h, 0.5f));
        clsf = (float)g_cls[b * NA + idx];
        off  = __fmul_rn(clsf, MAXWH);
    } else {
        score = 0.f;
    }
    float ox1 = __fadd_rn(x1, off), oy1 = __fadd_rn(y1, off);
    float ox2 = __fadd_rn(x2, off), oy2 = __fadd_rn(y2, off);
    if (!valid) { ox1 = oy1 = ox2 = oy2 = 0.f; }

    g_bx  [b * K_PRE + t] = make_float4(ox1, oy1, ox2, oy2);
    g_area[b * K_PRE + t] = __fmul_rn(__fsub_rn(ox2, ox1), __fsub_rn(oy2, oy1));
    g_raw [b * K_PRE + t] = make_float4(x1, y1, x2, y2);
    g_sc  [b * K_PRE + t] = make_float2(score, clsf);
}

// ---------------- kernel 5: full-chip suppression mask (64x64 tiles) ----------------
__global__ void mask_kernel() {
    int jt = blockIdx.x;   // suppressor tile (cols)
    int it = blockIdx.y;   // suppressee tile (rows)
    int b  = blockIdx.z;
    int t  = threadIdx.x;  // 64 threads: one row each
    int i  = it * 64 + t;

    uint32_t w0 = 0u, w1 = 0u;
    if (jt <= it) {
        __shared__ float4 jb[64];
        __shared__ float  ja[64];
        jb[t] = g_bx  [b * K_PRE + jt * 64 + t];
        ja[t] = g_area[b * K_PRE + jt * 64 + t];
        __syncthreads();

        float4 ib = g_bx  [b * K_PRE + i];
        float  ia = g_area[b * K_PRE + i];

        #pragma unroll 8
        for (int jj = 0; jj < 64; jj++) {
            int j = jt * 64 + jj;
            if (j >= i) break;                 // only higher-score (lower index) suppresses
            float4 ob = jb[jj];
            float ltx = fmaxf(ib.x, ob.x), lty = fmaxf(ib.y, ob.y);
            float rbx = fminf(ib.z, ob.z), rby = fminf(ib.w, ob.w);
            float ww = fmaxf(__fsub_rn(rbx, ltx), 0.0f);
            float hh = fmaxf(__fsub_rn(rby, lty), 0.0f);
            float inter = __fmul_rn(ww, hh);
            float uni   = __fadd_rn(__fsub_rn(__fadd_rn(ia, ja[jj]), inter), 1e-7f);
            float iou   = __fdiv_rn(inter, uni);
            if (iou > IOU_T) {
                if (jj < 32) w0 |= 1u << jj;
                else         w1 |= 1u << (jj - 32);
            }
        }
    }
    g_maskT[(b * 32 + jt * 2 + 0) * K_PRE + i] = w0;
    g_maskT[(b * 32 + jt * 2 + 1) * K_PRE + i] = w1;
}

// ---------------- kernel 6: Jacobi greedy-NMS resolution + output ----------------
__global__ void __launch_bounds__(1024, 1)
final_kernel(float* __restrict__ out) {
    int b = blockIdx.x;
    int t = threadIdx.x;

    __shared__ uint32_t keep_s[32];
    __shared__ int      pfx[33];

    if (t < MAX_DET * 6) out[b * MAX_DET * 6 + t] = 0.0f;

    float2 sc = g_sc[b * K_PRE + t];
    bool valid = sc.x > 0.0f;

    uint32_t row[32];
    #pragma unroll
    for (int w = 0; w < 32; w++) row[w] = g_maskT[(b * 32 + w) * K_PRE + t];

    {
        unsigned bal = __ballot_sync(0xffffffffu, valid);
        if ((t & 31) == 0) keep_s[t >> 5] = bal;
    }
    __syncthreads();

    for (int it = 0; it < K_PRE; it++) {
        uint32_t acc = 0;
        #pragma unroll
        for (int w = 0; w < 32; w++) acc |= row[w] & keep_s[w];
        int nb  = (valid && acc == 0) ? 1 : 0;
        int old = (keep_s[t >> 5] >> (t & 31)) & 1;
        __syncthreads();
        unsigned nbal = __ballot_sync(0xffffffffu, nb);
        if ((t & 31) == 0) keep_s[t >> 5] = nbal;
        int changed = __syncthreads_or(nb != old);
        if (!changed) break;
    }

    if (t == 0) {
        pfx[0] = 0;
        for (int w = 0; w < 32; w++) pfx[w + 1] = pfx[w] + __popc(keep_s[w]);
    }
    __syncthreads();

    uint32_t kw = keep_s[t >> 5];
    if (valid && ((kw >> (t & 31)) & 1)) {
        int rank = pfx[t >> 5] + __popc(kw & ((1u << (t & 31)) - 1u));
        if (rank < MAX_DET) {
            float4 r = g_raw[b * K_PRE + t];
            float* o = out + ((size_t)b * MAX_DET + rank) * 6;
            o[0] = r.x; o[1] = r.y; o[2] = r.z; o[3] = r.w;
            o[4] = sc.x; o[5] = sc.y;
        }
    }
}

// ---------------- launcher ----------------
extern "C" void kernel_launch(void* const* d_in, const int* in_sizes, int n_in,
                              void* d_out, int out_size) {
    (void)in_sizes; (void)n_in; (void)out_size;
    const float* pred = (const float*)d_in[0];
    float* out = (float*)d_out;

    zero_kernel  <<<(B * NBINS + 255) / 256, 256>>>();
    score_kernel <<<(B * NA) / G_ANCH, 256>>>(pred);
    thresh_kernel<<<B, 32>>>();
    gather_kernel<<<dim3((NA / 8 + 255) / 256, B), 256>>>();
    sort_kernel  <<<B, 1024>>>(pred);
    mask_kernel  <<<dim3(16, 16, B), 64>>>();
    final_kernel <<<B, 1024>>>(out);
}

// round 5
// speedup vs baseline: 2.8336x; 1.0753x over previous
#include <cuda_runtime.h>
#include <cstdint>

#define B       8
#define NA      100800
#define NC      85
#define K_PRE   1024
#define MAX_DET 100
#define NBINS   8192
#define CAP     2048
#define SORT_N  2048
#define CONF    0.25f
#define IOU_T   0.45f
#define MAXWH   7680.0f
#define S_ANCH  128                      // anchors per score block (== threads)

// ---------------- device scratch (no allocations allowed) ----------------
__device__ uint32_t           g_keys[B * NA];
__device__ uint8_t            g_cls [B * NA];
__device__ uint32_t           g_hist[B * NBINS];
__device__ int                g_T   [B];
__device__ int                g_cnt [B];
__device__ unsigned long long g_cand[B * CAP];
__device__ float4             g_bx  [B * K_PRE];   // class-offset boxes
__device__ float              g_area[B * K_PRE];
__device__ float4             g_raw [B * K_PRE];   // un-offset boxes (output)
__device__ float2             g_sc  [B * K_PRE];   // (score, cls)
// suppression bitmask, transposed: word w of row i at [(b*32+w)*1024 + i]
__device__ uint32_t           g_maskT[B * 32 * K_PRE];

// ---------------- kernel 0: zero histogram + counters ----------------
__global__ void zero_kernel() {
    int i = blockIdx.x * blockDim.x + threadIdx.x;
    if (i < B * NBINS) g_hist[i] = 0u;
    if (i < B)         g_cnt[i]  = 0;
}

// ---------------- kernel 1: score/cls — thread-per-anchor, no warp reductions ----------------
__global__ void __launch_bounds__(S_ANCH)
score_kernel(const float* __restrict__ pred) {
    __shared__ float sb[S_ANCH * NC];          // 128*85 floats = 43520 B
    int blk = blockIdx.x;                      // 6300 blocks; 128|NA -> no batch straddle
    int t   = threadIdx.x;

    // stage 128 anchors, perfectly coalesced float4 (block base 16B-aligned)
    const float4* src = (const float4*)(pred + (size_t)blk * (S_ANCH * NC));
    float4* dst = (float4*)sb;
    const int NV = (S_ANCH * NC) / 4;          // 2720
    #pragma unroll
    for (int r = 0; r < 22; r++) {
        int i = r * S_ANCH + t;
        if (i < NV) dst[i] = __ldcs(src + i);
    }
    __syncthreads();

    const float* p = sb + t * NC;              // lane stride 85 mod 32 = 21 -> conflict-free
    float obj = p[4];

    uint32_t key = 0u;
    uint32_t cls = 0u;
    if (obj > CONF) {
        // 4 blocked partial maxima (contiguous class ranges) -> tie order preserved
        float m0 = -1.f, m1 = -1.f, m2 = -1.f, m3 = -1.f;
        int   i0 = 0,    i1 = 0,    i2 = 0,    i3 = 0;
        #pragma unroll
        for (int k = 0; k < 20; k++) {
            float c0 = __fmul_rn(p[5 + k],      obj);
            float c1 = __fmul_rn(p[5 + 20 + k], obj);
            float c2 = __fmul_rn(p[5 + 40 + k], obj);
            float c3 = __fmul_rn(p[5 + 60 + k], obj);
            if (c0 > m0) { m0 = c0; i0 = k; }
            if (c1 > m1) { m1 = c1; i1 = 20 + k; }
            if (c2 > m2) { m2 = c2; i2 = 40 + k; }
            if (c3 > m3) { m3 = c3; i3 = 60 + k; }
        }
        // merge in ascending block order with strict > : lowest class wins ties
        float best = m0; int bid = i0;
        if (m1 > best) { best = m1; bid = i1; }
        if (m2 > best) { best = m2; bid = i2; }
        if (m3 > best) { best = m3; bid = i3; }

        if (best > CONF) {
            key = __float_as_uint(best);
            cls = (uint32_t)bid;
            int anchor = blk * S_ANCH + t;
            int b = anchor / NA;
            int bin = (int)(best * (float)NBINS);
            if (bin > NBINS - 1) bin = NBINS - 1;
            atomicAdd(&g_hist[b * NBINS + bin], 1u);
        }
    }
    int anchor = blk * S_ANCH + t;
    g_keys[anchor] = key;
    g_cls [anchor] = (uint8_t)cls;
}

// ---------------- kernel 2: per-batch threshold bin (top-K cutoff) ----------------
__global__ void thresh_kernel() {
    int b = blockIdx.x;
    int lane = threadIdx.x;
    const unsigned F = 0xffffffffu;
    int acc = 0;
    int T = 0;
    for (int hi = NBINS - 1; hi >= 31; hi -= 32) {
        int c = (int)g_hist[b * NBINS + hi - lane];
        int ps = c;
        for (int o = 1; o < 32; o <<= 1) {
            int v = __shfl_up_sync(F, ps, o);
            if (lane >= o) ps += v;
        }
        int tot = __shfl_sync(F, ps, 31);
        unsigned bal = __ballot_sync(F, acc + ps >= K_PRE);
        if (bal) { int l = __ffs(bal) - 1; T = hi - l; break; }
        acc += tot;
    }
    if (lane == 0) g_T[b] = T;
}

// ---------------- kernel 3: gather (block-aggregated atomics, 8 keys/thread) ----------------
__global__ void gather_kernel() {
    __shared__ int s_cnt, s_base;
    int b = blockIdx.y;
    int base = (blockIdx.x * blockDim.x + threadIdx.x) * 8;  // anchor idx within batch
    if (threadIdx.x == 0) s_cnt = 0;
    __syncthreads();

    uint32_t ks[8];
    int pos[8];
    bool pass[8] = {false,false,false,false,false,false,false,false};

    if (base < NA) {   // NA % 8 == 0 -> full vector or nothing
        const uint4* kp = (const uint4*)(g_keys + (size_t)b * NA + base);
        uint4 k0 = kp[0], k1 = kp[1];
        ks[0]=k0.x; ks[1]=k0.y; ks[2]=k0.z; ks[3]=k0.w;
        ks[4]=k1.x; ks[5]=k1.y; ks[6]=k1.z; ks[7]=k1.w;
        int T = g_T[b];
        #pragma unroll
        for (int u = 0; u < 8; u++) {
            uint32_t key = ks[u];
            if (!key) continue;
            float s = __uint_as_float(key);
            int bin = (int)(s * (float)NBINS);
            if (bin > NBINS - 1) bin = NBINS - 1;
            if (bin < T) continue;
            pos[u] = atomicAdd(&s_cnt, 1);
            pass[u] = true;
        }
    }
    __syncthreads();
    if (threadIdx.x == 0) s_base = (s_cnt > 0) ? atomicAdd(&g_cnt[b], s_cnt) : 0;
    __syncthreads();

    #pragma unroll
    for (int u = 0; u < 8; u++) {
        if (pass[u]) {
            int p = s_base + pos[u];
            if (p < CAP) {
                uint32_t li = (uint32_t)(base + u);
                g_cand[b * CAP + p] =
                    ((unsigned long long)ks[u] << 32) |
                    (unsigned long long)(0xFFFFFFFFu - li);
            }
        }
    }
}

// ---------------- kernel 4: bitonic sort + box precompute (one block/batch) ----------------
__global__ void __launch_bounds__(1024, 1)
sort_kernel(const float* __restrict__ pred) {
    __shared__ unsigned long long sb[SORT_N];
    int b = blockIdx.x;
    int t = threadIdx.x;

    int cnt = g_cnt[b];
    if (cnt > CAP) cnt = CAP;
    for (int id = t; id < SORT_N; id += 1024)
        sb[id] = (id < cnt) ? ~g_cand[b * CAP + id] : ~0ull;
    __syncthreads();

    for (int k = 2; k <= SORT_N; k <<= 1) {
        for (int j = k >> 1; j > 0; j >>= 1) {
            for (int id = t; id < SORT_N; id += 1024) {
                int ixj = id ^ j;
                if (ixj > id) {
                    unsigned long long x = sb[id], y = sb[ixj];
                    bool up = ((id & k) == 0);
                    if ((x > y) == up) { sb[id] = y; sb[ixj] = x; }
                }
            }
            __syncthreads();
        }
    }

    unsigned long long key = ~sb[t];   // element t of descending order (top 1024)
    bool  valid = (key != 0ull);
    float score = __uint_as_float((uint32_t)(key >> 32));
    uint32_t idx = 0xFFFFFFFFu - (uint32_t)key;

    float x1 = 0.f, y1 = 0.f, x2 = 0.f, y2 = 0.f, clsf = 0.f, off = 0.f;
    if (valid) {
        const float* pr = pred + ((size_t)b * NA + idx) * NC;
        float cx = pr[0], cy = pr[1], w = pr[2], h = pr[3];
        x1 = __fsub_rn(cx, __fmul_rn(w, 0.5f));
        y1 = __fsub_rn(cy, __fmul_rn(h, 0.5f));
        x2 = __fadd_rn(cx, __fmul_rn(w, 0.5f));
        y2 = __fadd_rn(cy, __fmul_rn(h, 0.5f));
        clsf = (float)g_cls[b * NA + idx];
        off  = __fmul_rn(clsf, MAXWH);
    } else {
        score = 0.f;
    }
    float ox1 = __fadd_rn(x1, off), oy1 = __fadd_rn(y1, off);
    float ox2 = __fadd_rn(x2, off), oy2 = __fadd_rn(y2, off);
    if (!valid) { ox1 = oy1 = ox2 = oy2 = 0.f; }

    g_bx  [b * K_PRE + t] = make_float4(ox1, oy1, ox2, oy2);
    g_area[b * K_PRE + t] = __fmul_rn(__fsub_rn(ox2, ox1), __fsub_rn(oy2, oy1));
    g_raw [b * K_PRE + t] = make_float4(x1, y1, x2, y2);
    g_sc  [b * K_PRE + t] = make_float2(score, clsf);
}

// ---------------- kernel 5: full-chip suppression mask (64x64 tiles) ----------------
__global__ void mask_kernel() {
    int jt = blockIdx.x;   // suppressor tile (cols)
    int it = blockIdx.y;   // suppressee tile (rows)
    int b  = blockIdx.z;
    int t  = threadIdx.x;  // 64 threads: one row each
    int i  = it * 64 + t;

    uint32_t w0 = 0u, w1 = 0u;
    if (jt <= it) {
        __shared__ float4 jb[64];
        __shared__ float  ja[64];
        jb[t] = g_bx  [b * K_PRE + jt * 64 + t];
        ja[t] = g_area[b * K_PRE + jt * 64 + t];
        __syncthreads();

        float4 ib = g_bx  [b * K_PRE + i];
        float  ia = g_area[b * K_PRE + i];

        #pragma unroll 8
        for (int jj = 0; jj < 64; jj++) {
            int j = jt * 64 + jj;
            if (j >= i) break;                 // only higher-score (lower index) suppresses
            float4 ob = jb[jj];
            float ltx = fmaxf(ib.x, ob.x), lty = fmaxf(ib.y, ob.y);
            float rbx = fminf(ib.z, ob.z), rby = fminf(ib.w, ob.w);
            float ww = fmaxf(__fsub_rn(rbx, ltx), 0.0f);
            float hh = fmaxf(__fsub_rn(rby, lty), 0.0f);
            float inter = __fmul_rn(ww, hh);
            float uni   = __fadd_rn(__fsub_rn(__fadd_rn(ia, ja[jj]), inter), 1e-7f);
            float iou   = __fdiv_rn(inter, uni);
            if (iou > IOU_T) {
                if (jj < 32) w0 |= 1u << jj;
                else         w1 |= 1u << (jj - 32);
            }
        }
    }
    g_maskT[(b * 32 + jt * 2 + 0) * K_PRE + i] = w0;
    g_maskT[(b * 32 + jt * 2 + 1) * K_PRE + i] = w1;
}

// ---------------- kernel 6: Jacobi greedy-NMS resolution + output ----------------
__global__ void __launch_bounds__(1024, 1)
final_kernel(float* __restrict__ out) {
    int b = blockIdx.x;
    int t = threadIdx.x;

    __shared__ uint32_t keep_s[32];
    __shared__ int      pfx[33];

    if (t < MAX_DET * 6) out[b * MAX_DET * 6 + t] = 0.0f;

    float2 sc = g_sc[b * K_PRE + t];
    bool valid = sc.x > 0.0f;

    uint32_t row[32];
    #pragma unroll
    for (int w = 0; w < 32; w++) row[w] = g_maskT[(b * 32 + w) * K_PRE + t];

    {
        unsigned bal = __ballot_sync(0xffffffffu, valid);
        if ((t & 31) == 0) keep_s[t >> 5] = bal;
    }
    __syncthreads();

    for (int it = 0; it < K_PRE; it++) {
        uint32_t acc = 0;
        #pragma unroll
        for (int w = 0; w < 32; w++) acc |= row[w] & keep_s[w];
        int nb  = (valid && acc == 0) ? 1 : 0;
        int old = (keep_s[t >> 5] >> (t & 31)) & 1;
        __syncthreads();
        unsigned nbal = __ballot_sync(0xffffffffu, nb);
        if ((t & 31) == 0) keep_s[t >> 5] = nbal;
        int changed = __syncthreads_or(nb != old);
        if (!changed) break;
    }

    if (t == 0) {
        pfx[0] = 0;
        for (int w = 0; w < 32; w++) pfx[w + 1] = pfx[w] + __popc(keep_s[w]);
    }
    __syncthreads();

    uint32_t kw = keep_s[t >> 5];
    if (valid && ((kw >> (t & 31)) & 1)) {
        int rank = pfx[t >> 5] + __popc(kw & ((1u << (t & 31)) - 1u));
        if (rank < MAX_DET) {
            float4 r = g_raw[b * K_PRE + t];
            float* o = out + ((size_t)b * MAX_DET + rank) * 6;
            o[0] = r.x; o[1] = r.y; o[2] = r.z; o[3] = r.w;
            o[4] = sc.x; o[5] = sc.y;
        }
    }
}

// ---------------- launcher ----------------
extern "C" void kernel_launch(void* const* d_in, const int* in_sizes, int n_in,
                              void* d_out, int out_size) {
    (void)in_sizes; (void)n_in; (void)out_size;
    const float* pred = (const float*)d_in[0];
    float* out = (float*)d_out;

    zero_kernel  <<<(B * NBINS + 255) / 256, 256>>>();
    score_kernel <<<(B * NA) / S_ANCH, S_ANCH>>>(pred);
    thresh_kernel<<<B, 32>>>();
    gather_kernel<<<dim3((NA / 8 + 255) / 256, B), 256>>>();
    sort_kernel  <<<B, 1024>>>(pred);
    mask_kernel  <<<dim3(16, 16, B), 64>>>();
    final_kernel <<<B, 1024>>>(out);
}

// round 6
// speedup vs baseline: 2.9335x; 1.0353x over previous
#include <cuda_runtime.h>
#include <cstdint>

#define B       8
#define NA      100800
#define NC      85
#define K_PRE   1024
#define MAX_DET 100
#define NBINS   8192
#define CAP     2048
#define SORT_N  2048
#define CONF    0.25f
#define IOU_T   0.45f
#define MAXWH   7680.0f

#define S_ANCH   128                        // anchors per tile (== threads per score block)
#define NT       ((B * NA) / S_ANCH)        // 6300 tiles (tiles may straddle batches: OK)
#define NV       ((S_ANCH * NC) / 4)        // 2720 float4 per tile
#define TILE_B   (S_ANCH * NC * 4)          // 43520 bytes per tile
#define SGRID    296                        // 2 blocks/SM

// ---------------- device scratch (no allocations allowed) ----------------
__device__ uint32_t           g_keys[B * NA];
__device__ uint8_t            g_cls [B * NA];
__device__ uint32_t           g_hist[B * NBINS];   // zero-init at load; re-zeroed by thresh
__device__ int                g_T   [B];
__device__ int                g_cnt [B];           // zero-init; re-zeroed by thresh
__device__ unsigned long long g_cand[B * CAP];
__device__ float4             g_bx  [B * K_PRE];
__device__ float              g_area[B * K_PRE];
__device__ float4             g_raw [B * K_PRE];
__device__ float2             g_sc  [B * K_PRE];
// suppression bitmask, transposed: word w of row i at [(b*32+w)*1024 + i]
__device__ uint32_t           g_maskT[B * 32 * K_PRE];

// ---------------- cp.async helpers ----------------
__device__ __forceinline__ void cp_async16(uint32_t saddr, const void* gptr) {
    asm volatile("cp.async.cg.shared.global [%0], [%1], 16;" :: "r"(saddr), "l"(gptr));
}
__device__ __forceinline__ void cp_commit() {
    asm volatile("cp.async.commit_group;");
}
template <int N>
__device__ __forceinline__ void cp_wait() {
    asm volatile("cp.async.wait_group %0;" :: "n"(N));
}

// ---------------- kernel 1: score/cls — cp.async double-buffered streaming ----------------
__global__ void __launch_bounds__(S_ANCH)
score_kernel(const float* __restrict__ pred) {
    extern __shared__ float sb[];               // 2 tiles: 2 * 128*85 floats = 87040 B
    int t = threadIdx.x;
    uint32_t sb_u32 = (uint32_t)__cvta_generic_to_shared(sb);

    // prologue: stage first tile into buffer 0
    int tile0 = blockIdx.x;
    if (tile0 < NT) {
        const float4* src = (const float4*)(pred + (size_t)tile0 * (S_ANCH * NC));
        #pragma unroll
        for (int r = 0; r < 22; r++) {
            int i = r * S_ANCH + t;
            if (i < NV) cp_async16(sb_u32 + i * 16, src + i);
        }
        cp_commit();
    }

    int parity = 0;
    for (int tile = tile0; tile < NT; tile += SGRID) {
        int next = tile + SGRID;
        if (next < NT) {
            uint32_t dst = sb_u32 + (parity ^ 1) * TILE_B;
            const float4* src = (const float4*)(pred + (size_t)next * (S_ANCH * NC));
            #pragma unroll
            for (int r = 0; r < 22; r++) {
                int i = r * S_ANCH + t;
                if (i < NV) cp_async16(dst + i * 16, src + i);
            }
            cp_commit();
            cp_wait<1>();                       // current tile's group complete
        } else {
            cp_wait<0>();
        }
        __syncthreads();

        // ---- compute current tile (identical arithmetic to round 5) ----
        const float* p = sb + parity * (S_ANCH * NC) + t * NC;  // stride 85: conflict-free
        float obj = p[4];

        uint32_t key = 0u;
        uint32_t cls = 0u;
        if (obj > CONF) {
            float m0 = -1.f, m1 = -1.f, m2 = -1.f, m3 = -1.f;
            int   i0 = 0,    i1 = 0,    i2 = 0,    i3 = 0;
            #pragma unroll
            for (int k = 0; k < 20; k++) {
                float c0 = __fmul_rn(p[5 + k],      obj);
                float c1 = __fmul_rn(p[5 + 20 + k], obj);
                float c2 = __fmul_rn(p[5 + 40 + k], obj);
                float c3 = __fmul_rn(p[5 + 60 + k], obj);
                if (c0 > m0) { m0 = c0; i0 = k; }
                if (c1 > m1) { m1 = c1; i1 = 20 + k; }
                if (c2 > m2) { m2 = c2; i2 = 40 + k; }
                if (c3 > m3) { m3 = c3; i3 = 60 + k; }
            }
            float best = m0; int bid = i0;
            if (m1 > best) { best = m1; bid = i1; }
            if (m2 > best) { best = m2; bid = i2; }
            if (m3 > best) { best = m3; bid = i3; }

            if (best > CONF) {
                key = __float_as_uint(best);
                cls = (uint32_t)bid;
                int anchor = tile * S_ANCH + t;
                int b = anchor / NA;
                int bin = (int)(best * (float)NBINS);
                if (bin > NBINS - 1) bin = NBINS - 1;
                atomicAdd(&g_hist[b * NBINS + bin], 1u);
            }
        }
        int anchor = tile * S_ANCH + t;
        g_keys[anchor] = key;
        g_cls [anchor] = (uint8_t)cls;

        __syncthreads();                        // protect buffer before next prefetch
        parity ^= 1;
    }
}

// ---------------- kernel 2: threshold bin + state reset (folded zero) ----------------
__global__ void __launch_bounds__(1024)
thresh_kernel() {
    int b = blockIdx.x;
    int t = threadIdx.x;
    int lane = t & 31;
    const unsigned F = 0xffffffffu;

    if (t < 32) {   // warp 0 computes the cutoff
        int acc = 0;
        int T = 0;
        for (int hi = NBINS - 1; hi >= 31; hi -= 32) {
            int c = (int)g_hist[b * NBINS + hi - lane];
            int ps = c;
            for (int o = 1; o < 32; o <<= 1) {
                int v = __shfl_up_sync(F, ps, o);
                if (lane >= o) ps += v;
            }
            int tot = __shfl_sync(F, ps, 31);
            unsigned bal = __ballot_sync(F, acc + ps >= K_PRE);
            if (bal) { int l = __ffs(bal) - 1; T = hi - l; break; }
            acc += tot;
        }
        if (lane == 0) { g_T[b] = T; g_cnt[b] = 0; }
    }
    __syncthreads();
    // re-zero this batch's histogram for the next graph replay
    #pragma unroll
    for (int r = 0; r < NBINS / 1024; r++)
        g_hist[b * NBINS + r * 1024 + t] = 0u;
}

// ---------------- kernel 3: gather (block-aggregated atomics, 8 keys/thread) ----------------
__global__ void gather_kernel() {
    __shared__ int s_cnt, s_base;
    int b = blockIdx.y;
    int base = (blockIdx.x * blockDim.x + threadIdx.x) * 8;
    if (threadIdx.x == 0) s_cnt = 0;
    __syncthreads();

    uint32_t ks[8];
    int pos[8];
    bool pass[8] = {false,false,false,false,false,false,false,false};

    if (base < NA) {   // NA % 8 == 0
        const uint4* kp = (const uint4*)(g_keys + (size_t)b * NA + base);
        uint4 k0 = kp[0], k1 = kp[1];
        ks[0]=k0.x; ks[1]=k0.y; ks[2]=k0.z; ks[3]=k0.w;
        ks[4]=k1.x; ks[5]=k1.y; ks[6]=k1.z; ks[7]=k1.w;
        int T = g_T[b];
        #pragma unroll
        for (int u = 0; u < 8; u++) {
            uint32_t key = ks[u];
            if (!key) continue;
            float s = __uint_as_float(key);
            int bin = (int)(s * (float)NBINS);
            if (bin > NBINS - 1) bin = NBINS - 1;
            if (bin < T) continue;
            pos[u] = atomicAdd(&s_cnt, 1);
            pass[u] = true;
        }
    }
    __syncthreads();
    if (threadIdx.x == 0) s_base = (s_cnt > 0) ? atomicAdd(&g_cnt[b], s_cnt) : 0;
    __syncthreads();

    #pragma unroll
    for (int u = 0; u < 8; u++) {
        if (pass[u]) {
            int p = s_base + pos[u];
            if (p < CAP) {
                uint32_t li = (uint32_t)(base + u);
                g_cand[b * CAP + p] =
                    ((unsigned long long)ks[u] << 32) |
                    (unsigned long long)(0xFFFFFFFFu - li);
            }
        }
    }
}

// ---------------- kernel 4: bitonic sort + box precompute (one block/batch) ----------------
__global__ void __launch_bounds__(1024, 1)
sort_kernel(const float* __restrict__ pred) {
    __shared__ unsigned long long sb[SORT_N];
    int b = blockIdx.x;
    int t = threadIdx.x;

    int cnt = g_cnt[b];
    if (cnt > CAP) cnt = CAP;
    for (int id = t; id < SORT_N; id += 1024)
        sb[id] = (id < cnt) ? ~g_cand[b * CAP + id] : ~0ull;
    __syncthreads();

    for (int k = 2; k <= SORT_N; k <<= 1) {
        for (int j = k >> 1; j > 0; j >>= 1) {
            for (int id = t; id < SORT_N; id += 1024) {
                int ixj = id ^ j;
                if (ixj > id) {
                    unsigned long long x = sb[id], y = sb[ixj];
                    bool up = ((id & k) == 0);
                    if ((x > y) == up) { sb[id] = y; sb[ixj] = x; }
                }
            }
            __syncthreads();
        }
    }

    unsigned long long key = ~sb[t];
    bool  valid = (key != 0ull);
    float score = __uint_as_float((uint32_t)(key >> 32));
    uint32_t idx = 0xFFFFFFFFu - (uint32_t)key;

    float x1 = 0.f, y1 = 0.f, x2 = 0.f, y2 = 0.f, clsf = 0.f, off = 0.f;
    if (valid) {
        const float* pr = pred + ((size_t)b * NA + idx) * NC;
        float cx = pr[0], cy = pr[1], w = pr[2], h = pr[3];
        x1 = __fsub_rn(cx, __fmul_rn(w, 0.5f));
        y1 = __fsub_rn(cy, __fmul_rn(h, 0.5f));
        x2 = __fadd_rn(cx, __fmul_rn(w, 0.5f));
        y2 = __fadd_rn(cy, __fmul_rn(h, 0.5f));
        clsf = (float)g_cls[b * NA + idx];
        off  = __fmul_rn(clsf, MAXWH);
    } else {
        score = 0.f;
    }
    float ox1 = __fadd_rn(x1, off), oy1 = __fadd_rn(y1, off);
    float ox2 = __fadd_rn(x2, off), oy2 = __fadd_rn(y2, off);
    if (!valid) { ox1 = oy1 = ox2 = oy2 = 0.f; }

    g_bx  [b * K_PRE + t] = make_float4(ox1, oy1, ox2, oy2);
    g_area[b * K_PRE + t] = __fmul_rn(__fsub_rn(ox2, ox1), __fsub_rn(oy2, oy1));
    g_raw [b * K_PRE + t] = make_float4(x1, y1, x2, y2);
    g_sc  [b * K_PRE + t] = make_float2(score, clsf);
}

// ---------------- kernel 5: full-chip suppression mask (64x64 tiles) ----------------
__global__ void mask_kernel() {
    int jt = blockIdx.x;
    int it = blockIdx.y;
    int b  = blockIdx.z;
    int t  = threadIdx.x;
    int i  = it * 64 + t;

    uint32_t w0 = 0u, w1 = 0u;
    if (jt <= it) {
        __shared__ float4 jb[64];
        __shared__ float  ja[64];
        jb[t] = g_bx  [b * K_PRE + jt * 64 + t];
        ja[t] = g_area[b * K_PRE + jt * 64 + t];
        __syncthreads();

        float4 ib = g_bx  [b * K_PRE + i];
        float  ia = g_area[b * K_PRE + i];

        #pragma unroll 8
        for (int jj = 0; jj < 64; jj++) {
            int j = jt * 64 + jj;
            if (j >= i) break;
            float4 ob = jb[jj];
            float ltx = fmaxf(ib.x, ob.x), lty = fmaxf(ib.y, ob.y);
            float rbx = fminf(ib.z, ob.z), rby = fminf(ib.w, ob.w);
            float ww = fmaxf(__fsub_rn(rbx, ltx), 0.0f);
            float hh = fmaxf(__fsub_rn(rby, lty), 0.0f);
            float inter = __fmul_rn(ww, hh);
            float uni   = __fadd_rn(__fsub_rn(__fadd_rn(ia, ja[jj]), inter), 1e-7f);
            float iou   = __fdiv_rn(inter, uni);
            if (iou > IOU_T) {
                if (jj < 32) w0 |= 1u << jj;
                else         w1 |= 1u << (jj - 32);
            }
        }
    }
    g_maskT[(b * 32 + jt * 2 + 0) * K_PRE + i] = w0;
    g_maskT[(b * 32 + jt * 2 + 1) * K_PRE + i] = w1;
}

// ---------------- kernel 6: Jacobi greedy-NMS resolution + output ----------------
__global__ void __launch_bounds__(1024, 1)
final_kernel(float* __restrict__ out) {
    int b = blockIdx.x;
    int t = threadIdx.x;

    __shared__ uint32_t keep_s[32];
    __shared__ int      pfx[33];

    if (t < MAX_DET * 6) out[b * MAX_DET * 6 + t] = 0.0f;

    float2 sc = g_sc[b * K_PRE + t];
    bool valid = sc.x > 0.0f;

    uint32_t row[32];
    #pragma unroll
    for (int w = 0; w < 32; w++) row[w] = g_maskT[(b * 32 + w) * K_PRE + t];

    {
        unsigned bal = __ballot_sync(0xffffffffu, valid);
        if ((t & 31) == 0) keep_s[t >> 5] = bal;
    }
    __syncthreads();

    for (int it = 0; it < K_PRE; it++) {
        uint32_t acc = 0;
        #pragma unroll
        for (int w = 0; w < 32; w++) acc |= row[w] & keep_s[w];
        int nb  = (valid && acc == 0) ? 1 : 0;
        int old = (keep_s[t >> 5] >> (t & 31)) & 1;
        __syncthreads();
        unsigned nbal = __ballot_sync(0xffffffffu, nb);
        if ((t & 31) == 0) keep_s[t >> 5] = nbal;
        int changed = __syncthreads_or(nb != old);
        if (!changed) break;
    }

    if (t == 0) {
        pfx[0] = 0;
        for (int w = 0; w < 32; w++) pfx[w + 1] = pfx[w] + __popc(keep_s[w]);
    }
    __syncthreads();

    uint32_t kw = keep_s[t >> 5];
    if (valid && ((kw >> (t & 31)) & 1)) {
        int rank = pfx[t >> 5] + __popc(kw & ((1u << (t & 31)) - 1u));
        if (rank < MAX_DET) {
            float4 r = g_raw[b * K_PRE + t];
            float* o = out + ((size_t)b * MAX_DET + rank) * 6;
            o[0] = r.x; o[1] = r.y; o[2] = r.z; o[3] = r.w;
            o[4] = sc.x; o[5] = sc.y;
        }
    }
}

// ---------------- launcher ----------------
extern "C" void kernel_launch(void* const* d_in, const int* in_sizes, int n_in,
                              void* d_out, int out_size) {
    (void)in_sizes; (void)n_in; (void)out_size;
    const float* pred = (const float*)d_in[0];
    float* out = (float*)d_out;

    static int configured = 0;
    if (!configured) {
        cudaFuncSetAttribute(score_kernel,
                             cudaFuncAttributeMaxDynamicSharedMemorySize, 2 * TILE_B);
        configured = 1;
    }

    score_kernel <<<SGRID, S_ANCH, 2 * TILE_B>>>(pred);
    thresh_kernel<<<B, 1024>>>();
    gather_kernel<<<dim3((NA / 8 + 255) / 256, B), 256>>>();
    sort_kernel  <<<B, 1024>>>(pred);
    mask_kernel  <<<dim3(16, 16, B), 64>>>();
    final_kernel <<<B, 1024>>>(out);
}

// round 7
// speedup vs baseline: 3.2545x; 1.1094x over previous
#include <cuda_runtime.h>
#include <cstdint>

#define B       8
#define NA      100800
#define NC      85
#define K_PRE   1024
#define MAX_DET 100
#define NBINS   8192
#define CAP     2048
#define CONF    0.25f
#define IOU_T   0.45f
#define MAXWH   7680.0f

#define S_ANCH   128                        // anchors per tile (== threads per score block)
#define NT       ((B * NA) / S_ANCH)        // 6300 tiles
#define NV       ((S_ANCH * NC) / 4)        // 2720 float4 per tile
#define TILE_B   (S_ANCH * NC * 4)          // 43520 bytes per tile
#define SGRID    296                        // 2 blocks/SM

// ---------------- device scratch (no allocations allowed) ----------------
__device__ uint32_t           g_keys[B * NA];
__device__ uint8_t            g_cls [B * NA];
__device__ uint32_t           g_hist[B * NBINS];   // zero-init at load; re-zeroed by thresh
__device__ int                g_T   [B];
__device__ int                g_cnt [B];           // zero-init; re-zeroed by thresh
__device__ unsigned long long g_cand[B * CAP];
__device__ float4             g_bx  [B * K_PRE];
__device__ float              g_area[B * K_PRE];
__device__ float4             g_raw [B * K_PRE];
__device__ float2             g_sc  [B * K_PRE];
// suppression bitmask, transposed: word w of row i at [(b*32+w)*1024 + i]
__device__ uint32_t           g_maskT[B * 32 * K_PRE];

// ---------------- cp.async helpers ----------------
__device__ __forceinline__ void cp_async16(uint32_t saddr, const void* gptr) {
    asm volatile("cp.async.cg.shared.global [%0], [%1], 16;" :: "r"(saddr), "l"(gptr));
}
__device__ __forceinline__ void cp_commit() {
    asm volatile("cp.async.commit_group;");
}
template <int N>
__device__ __forceinline__ void cp_wait() {
    asm volatile("cp.async.wait_group %0;" :: "n"(N));
}

// ---------------- kernel 1: score/cls — cp.async double-buffered streaming ----------------
__global__ void __launch_bounds__(S_ANCH)
score_kernel(const float* __restrict__ pred) {
    extern __shared__ float sb[];               // 2 tiles: 87040 B
    int t = threadIdx.x;
    uint32_t sb_u32 = (uint32_t)__cvta_generic_to_shared(sb);

    int tile0 = blockIdx.x;
    if (tile0 < NT) {
        const float4* src = (const float4*)(pred + (size_t)tile0 * (S_ANCH * NC));
        #pragma unroll
        for (int r = 0; r < 22; r++) {
            int i = r * S_ANCH + t;
            if (i < NV) cp_async16(sb_u32 + i * 16, src + i);
        }
        cp_commit();
    }

    int parity = 0;
    for (int tile = tile0; tile < NT; tile += SGRID) {
        int next = tile + SGRID;
        if (next < NT) {
            uint32_t dst = sb_u32 + (parity ^ 1) * TILE_B;
            const float4* src = (const float4*)(pred + (size_t)next * (S_ANCH * NC));
            #pragma unroll
            for (int r = 0; r < 22; r++) {
                int i = r * S_ANCH + t;
                if (i < NV) cp_async16(dst + i * 16, src + i);
            }
            cp_commit();
            cp_wait<1>();
        } else {
            cp_wait<0>();
        }
        __syncthreads();

        const float* p = sb + parity * (S_ANCH * NC) + t * NC;  // stride 85: conflict-free
        float obj = p[4];

        uint32_t key = 0u;
        uint32_t cls = 0u;
        if (obj > CONF) {
            float m0 = -1.f, m1 = -1.f, m2 = -1.f, m3 = -1.f;
            int   i0 = 0,    i1 = 0,    i2 = 0,    i3 = 0;
            #pragma unroll
            for (int k = 0; k < 20; k++) {
                float c0 = __fmul_rn(p[5 + k],      obj);
                float c1 = __fmul_rn(p[5 + 20 + k], obj);
                float c2 = __fmul_rn(p[5 + 40 + k], obj);
                float c3 = __fmul_rn(p[5 + 60 + k], obj);
                if (c0 > m0) { m0 = c0; i0 = k; }
                if (c1 > m1) { m1 = c1; i1 = 20 + k; }
                if (c2 > m2) { m2 = c2; i2 = 40 + k; }
                if (c3 > m3) { m3 = c3; i3 = 60 + k; }
            }
            float best = m0; int bid = i0;
            if (m1 > best) { best = m1; bid = i1; }
            if (m2 > best) { best = m2; bid = i2; }
            if (m3 > best) { best = m3; bid = i3; }

            if (best > CONF) {
                key = __float_as_uint(best);
                cls = (uint32_t)bid;
                int anchor = tile * S_ANCH + t;
                int b = anchor / NA;
                int bin = (int)(best * (float)NBINS);
                if (bin > NBINS - 1) bin = NBINS - 1;
                atomicAdd(&g_hist[b * NBINS + bin], 1u);
            }
        }
        int anchor = tile * S_ANCH + t;
        g_keys[anchor] = key;
        g_cls [anchor] = (uint8_t)cls;

        __syncthreads();
        parity ^= 1;
    }
}

// ---------------- kernel 2: threshold bin + state reset + slot pre-zero ----------------
__global__ void __launch_bounds__(1024)
thresh_kernel() {
    int b = blockIdx.x;
    int t = threadIdx.x;
    int lane = t & 31;
    const unsigned F = 0xffffffffu;

    if (t < 32) {   // warp 0 computes the cutoff
        int acc = 0;
        int T = 0;
        for (int hi = NBINS - 1; hi >= 31; hi -= 32) {
            int c = (int)g_hist[b * NBINS + hi - lane];
            int ps = c;
            for (int o = 1; o < 32; o <<= 1) {
                int v = __shfl_up_sync(F, ps, o);
                if (lane >= o) ps += v;
            }
            int tot = __shfl_sync(F, ps, 31);
            unsigned bal = __ballot_sync(F, acc + ps >= K_PRE);
            if (bal) { int l = __ffs(bal) - 1; T = hi - l; break; }
            acc += tot;
        }
        if (lane == 0) { g_T[b] = T; g_cnt[b] = 0; }
    }
    // pre-zero sorted-slot arrays (rank_kernel scatters over these)
    g_sc  [b * K_PRE + t] = make_float2(0.f, 0.f);
    g_bx  [b * K_PRE + t] = make_float4(0.f, 0.f, 0.f, 0.f);
    g_area[b * K_PRE + t] = 0.f;
    __syncthreads();
    // re-zero this batch's histogram for the next graph replay
    #pragma unroll
    for (int r = 0; r < NBINS / 1024; r++)
        g_hist[b * NBINS + r * 1024 + t] = 0u;
}

// ---------------- kernel 3: gather (block-aggregated atomics, 2 keys/thread) ----------------
__global__ void gather_kernel() {
    __shared__ int s_cnt, s_base;
    int b = blockIdx.y;
    int base = (blockIdx.x * blockDim.x + threadIdx.x) * 2;
    if (threadIdx.x == 0) s_cnt = 0;
    __syncthreads();

    uint32_t ks[2] = {0u, 0u};
    int pos[2];
    bool pass[2] = {false, false};

    if (base < NA) {   // NA even -> both lanes valid
        uint2 k2 = *(const uint2*)(g_keys + (size_t)b * NA + base);
        ks[0] = k2.x; ks[1] = k2.y;
        int T = g_T[b];
        #pragma unroll
        for (int u = 0; u < 2; u++) {
            uint32_t key = ks[u];
            if (!key) continue;
            float s = __uint_as_float(key);
            int bin = (int)(s * (float)NBINS);
            if (bin > NBINS - 1) bin = NBINS - 1;
            if (bin < T) continue;
            pos[u] = atomicAdd(&s_cnt, 1);
            pass[u] = true;
        }
    }
    __syncthreads();
    if (threadIdx.x == 0) s_base = (s_cnt > 0) ? atomicAdd(&g_cnt[b], s_cnt) : 0;
    __syncthreads();

    #pragma unroll
    for (int u = 0; u < 2; u++) {
        if (pass[u]) {
            int p = s_base + pos[u];
            if (p < CAP) {
                uint32_t li = (uint32_t)(base + u);
                g_cand[b * CAP + p] =
                    ((unsigned long long)ks[u] << 32) |
                    (unsigned long long)(0xFFFFFFFFu - li);
            }
        }
    }
}

// ---------------- kernel 4: rank-by-counting + scatter + box precompute ----------------
// rank(i) = #{j : key_j > key_i}; keys are distinct (composite with ~idx).
__global__ void __launch_bounds__(256)
rank_kernel(const float* __restrict__ pred) {
    __shared__ unsigned long long sk[CAP];
    int b = blockIdx.y;
    int cnt = g_cnt[b];
    if (cnt > CAP) cnt = CAP;
    if ((int)blockIdx.x * 256 >= cnt) return;

    for (int i = threadIdx.x; i < cnt; i += 256)
        sk[i] = g_cand[b * CAP + i];
    __syncthreads();

    int i = blockIdx.x * 256 + threadIdx.x;
    if (i >= cnt) return;
    unsigned long long ki = sk[i];

    int rank = 0;
    int j = 0;
    for (; j + 4 <= cnt; j += 4) {          // broadcast smem reads, conflict-free
        rank += (sk[j]     > ki);
        rank += (sk[j + 1] > ki);
        rank += (sk[j + 2] > ki);
        rank += (sk[j + 3] > ki);
    }
    for (; j < cnt; j++) rank += (sk[j] > ki);
    if (rank >= K_PRE) return;

    float score = __uint_as_float((uint32_t)(ki >> 32));
    uint32_t idx = 0xFFFFFFFFu - (uint32_t)ki;

    const float* pr = pred + ((size_t)b * NA + idx) * NC;
    float cx = pr[0], cy = pr[1], w = pr[2], h = pr[3];
    float x1 = __fsub_rn(cx, __fmul_rn(w, 0.5f));
    float y1 = __fsub_rn(cy, __fmul_rn(h, 0.5f));
    float x2 = __fadd_rn(cx, __fmul_rn(w, 0.5f));
    float y2 = __fadd_rn(cy, __fmul_rn(h, 0.5f));
    float clsf = (float)g_cls[b * NA + idx];
    float off  = __fmul_rn(clsf, MAXWH);

    float ox1 = __fadd_rn(x1, off), oy1 = __fadd_rn(y1, off);
    float ox2 = __fadd_rn(x2, off), oy2 = __fadd_rn(y2, off);

    int s = b * K_PRE + rank;
    g_bx  [s] = make_float4(ox1, oy1, ox2, oy2);
    g_area[s] = __fmul_rn(__fsub_rn(ox2, ox1), __fsub_rn(oy2, oy1));
    g_raw [s] = make_float4(x1, y1, x2, y2);
    g_sc  [s] = make_float2(score, clsf);
}

// ---------------- kernel 5: full-chip suppression mask (64x64 tiles) ----------------
__global__ void mask_kernel() {
    int jt = blockIdx.x;
    int it = blockIdx.y;
    int b  = blockIdx.z;
    int t  = threadIdx.x;
    int i  = it * 64 + t;

    uint32_t w0 = 0u, w1 = 0u;
    if (jt <= it) {
        __shared__ float4 jb[64];
        __shared__ float  ja[64];
        jb[t] = g_bx  [b * K_PRE + jt * 64 + t];
        ja[t] = g_area[b * K_PRE + jt * 64 + t];
        __syncthreads();

        float4 ib = g_bx  [b * K_PRE + i];
        float  ia = g_area[b * K_PRE + i];

        #pragma unroll 8
        for (int jj = 0; jj < 64; jj++) {
            int j = jt * 64 + jj;
            if (j >= i) break;
            float4 ob = jb[jj];
            float ltx = fmaxf(ib.x, ob.x), lty = fmaxf(ib.y, ob.y);
            float rbx = fminf(ib.z, ob.z), rby = fminf(ib.w, ob.w);
            float ww = fmaxf(__fsub_rn(rbx, ltx), 0.0f);
            float hh = fmaxf(__fsub_rn(rby, lty), 0.0f);
            float inter = __fmul_rn(ww, hh);
            float uni   = __fadd_rn(__fsub_rn(__fadd_rn(ia, ja[jj]), inter), 1e-7f);
            float iou   = __fdiv_rn(inter, uni);
            if (iou > IOU_T) {
                if (jj < 32) w0 |= 1u << jj;
                else         w1 |= 1u << (jj - 32);
            }
        }
    }
    g_maskT[(b * 32 + jt * 2 + 0) * K_PRE + i] = w0;
    g_maskT[(b * 32 + jt * 2 + 1) * K_PRE + i] = w1;
}

// ---------------- kernel 6: Jacobi greedy-NMS resolution + output ----------------
__global__ void __launch_bounds__(1024, 1)
final_kernel(float* __restrict__ out) {
    int b = blockIdx.x;
    int t = threadIdx.x;

    __shared__ uint32_t keep_s[32];
    __shared__ int      pfx[33];

    if (t < MAX_DET * 6) out[b * MAX_DET * 6 + t] = 0.0f;

    float2 sc = g_sc[b * K_PRE + t];
    bool valid = sc.x > 0.0f;

    uint32_t row[32];
    #pragma unroll
    for (int w = 0; w < 32; w++) row[w] = g_maskT[(b * 32 + w) * K_PRE + t];

    {
        unsigned bal = __ballot_sync(0xffffffffu, valid);
        if ((t & 31) == 0) keep_s[t >> 5] = bal;
    }
    __syncthreads();

    for (int it = 0; it < K_PRE; it++) {
        uint32_t acc = 0;
        #pragma unroll
        for (int w = 0; w < 32; w++) acc |= row[w] & keep_s[w];
        int nb  = (valid && acc == 0) ? 1 : 0;
        int old = (keep_s[t >> 5] >> (t & 31)) & 1;
        __syncthreads();
        unsigned nbal = __ballot_sync(0xffffffffu, nb);
        if ((t & 31) == 0) keep_s[t >> 5] = nbal;
        int changed = __syncthreads_or(nb != old);
        if (!changed) break;
    }

    if (t == 0) {
        pfx[0] = 0;
        for (int w = 0; w < 32; w++) pfx[w + 1] = pfx[w] + __popc(keep_s[w]);
    }
    __syncthreads();

    uint32_t kw = keep_s[t >> 5];
    if (valid && ((kw >> (t & 31)) & 1)) {
        int rank = pfx[t >> 5] + __popc(kw & ((1u << (t & 31)) - 1u));
        if (rank < MAX_DET) {
            float4 r = g_raw[b * K_PRE + t];
            float* o = out + ((size_t)b * MAX_DET + rank) * 6;
            o[0] = r.x; o[1] = r.y; o[2] = r.z; o[3] = r.w;
            o[4] = sc.x; o[5] = sc.y;
        }
    }
}

// ---------------- launcher ----------------
extern "C" void kernel_launch(void* const* d_in, const int* in_sizes, int n_in,
                              void* d_out, int out_size) {
    (void)in_sizes; (void)n_in; (void)out_size;
    const float* pred = (const float*)d_in[0];
    float* out = (float*)d_out;

    static int configured = 0;
    if (!configured) {
        cudaFuncSetAttribute(score_kernel,
                             cudaFuncAttributeMaxDynamicSharedMemorySize, 2 * TILE_B);
        configured = 1;
    }

    score_kernel <<<SGRID, S_ANCH, 2 * TILE_B>>>(pred);
    thresh_kernel<<<B, 1024>>>();
    gather_kernel<<<dim3((NA / 2 + 255) / 256, B), 256>>>();
    rank_kernel  <<<dim3(CAP / 256, B), 256>>>(pred);
    mask_kernel  <<<dim3(16, 16, B), 64>>>();
    final_kernel <<<B, 1024>>>(out);
}

// round 8
// speedup vs baseline: 3.4461x; 1.0588x over previous
#include <cuda_runtime.h>
#include <cstdint>

#define B       8
#define NA      100800
#define NC      85
#define K_PRE   1024
#define MAX_DET 100
#define NBINS   8192
#define CAP     2048
#define CONF    0.25f
#define IOU_T   0.45f
#define MAXWH   7680.0f

#define S_ANCH   128                        // anchors per tile (== threads per score block)
#define NT       ((B * NA) / S_ANCH)        // 6300 tiles
#define NV       ((S_ANCH * NC) / 4)        // 2720 float4 per tile
#define TILE_B   (S_ANCH * NC * 4)          // 43520 bytes per tile
#define SGRID    296                        // 2 blocks/SM

// ---------------- device scratch (no allocations allowed) ----------------
__device__ uint32_t           g_keys[B * NA];
__device__ uint8_t            g_cls [B * NA];
__device__ uint32_t           g_hist[B * NBINS];   // zero-init at load; re-zeroed by thresh
__device__ int                g_T   [B];
__device__ int                g_cnt [B];           // zero-init; re-zeroed by thresh
__device__ unsigned long long g_cand[B * CAP];
__device__ float4             g_bx  [B * K_PRE];
__device__ float              g_area[B * K_PRE];
__device__ float4             g_raw [B * K_PRE];
__device__ float2             g_sc  [B * K_PRE];
// suppression bitmask, transposed: word w of row i at [(b*32+w)*1024 + i]
__device__ uint32_t           g_maskT[B * 32 * K_PRE];

// ---------------- cp.async helpers ----------------
__device__ __forceinline__ void cp_async16(uint32_t saddr, const void* gptr) {
    asm volatile("cp.async.cg.shared.global [%0], [%1], 16;" :: "r"(saddr), "l"(gptr));
}
__device__ __forceinline__ void cp_commit() {
    asm volatile("cp.async.commit_group;");
}
template <int N>
__device__ __forceinline__ void cp_wait() {
    asm volatile("cp.async.wait_group %0;" :: "n"(N));
}

// ---------------- kernel 1: score/cls — cp.async double-buffered streaming ----------------
__global__ void __launch_bounds__(S_ANCH)
score_kernel(const float* __restrict__ pred) {
    extern __shared__ float sb[];               // 2 tiles: 87040 B
    int t = threadIdx.x;
    uint32_t sb_u32 = (uint32_t)__cvta_generic_to_shared(sb);

    int tile0 = blockIdx.x;
    if (tile0 < NT) {
        const float4* src = (const float4*)(pred + (size_t)tile0 * (S_ANCH * NC));
        #pragma unroll
        for (int r = 0; r < 22; r++) {
            int i = r * S_ANCH + t;
            if (i < NV) cp_async16(sb_u32 + i * 16, src + i);
        }
        cp_commit();
    }

    int parity = 0;
    for (int tile = tile0; tile < NT; tile += SGRID) {
        int next = tile + SGRID;
        if (next < NT) {
            uint32_t dst = sb_u32 + (parity ^ 1) * TILE_B;
            const float4* src = (const float4*)(pred + (size_t)next * (S_ANCH * NC));
            #pragma unroll
            for (int r = 0; r < 22; r++) {
                int i = r * S_ANCH + t;
                if (i < NV) cp_async16(dst + i * 16, src + i);
            }
            cp_commit();
            cp_wait<1>();
        } else {
            cp_wait<0>();
        }
        __syncthreads();

        const float* p = sb + parity * (S_ANCH * NC) + t * NC;  // stride 85: conflict-free
        float obj = p[4];

        uint32_t key = 0u;
        uint32_t cls = 0u;
        if (obj > CONF) {
            float m0 = -1.f, m1 = -1.f, m2 = -1.f, m3 = -1.f;
            int   i0 = 0,    i1 = 0,    i2 = 0,    i3 = 0;
            #pragma unroll
            for (int k = 0; k < 20; k++) {
                float c0 = __fmul_rn(p[5 + k],      obj);
                float c1 = __fmul_rn(p[5 + 20 + k], obj);
                float c2 = __fmul_rn(p[5 + 40 + k], obj);
                float c3 = __fmul_rn(p[5 + 60 + k], obj);
                if (c0 > m0) { m0 = c0; i0 = k; }
                if (c1 > m1) { m1 = c1; i1 = 20 + k; }
                if (c2 > m2) { m2 = c2; i2 = 40 + k; }
                if (c3 > m3) { m3 = c3; i3 = 60 + k; }
            }
            float best = m0; int bid = i0;
            if (m1 > best) { best = m1; bid = i1; }
            if (m2 > best) { best = m2; bid = i2; }
            if (m3 > best) { best = m3; bid = i3; }

            if (best > CONF) {
                key = __float_as_uint(best);
                cls = (uint32_t)bid;
                int anchor = tile * S_ANCH + t;
                int b = anchor / NA;
                int bin = (int)(best * (float)NBINS);
                if (bin > NBINS - 1) bin = NBINS - 1;
                atomicAdd(&g_hist[b * NBINS + bin], 1u);
            }
        }
        int anchor = tile * S_ANCH + t;
        g_keys[anchor] = key;
        g_cls [anchor] = (uint8_t)cls;

        __syncthreads();
        parity ^= 1;
    }
}

// ---------------- kernel 2: threshold bin + state reset + slot pre-zero ----------------
__global__ void __launch_bounds__(1024)
thresh_kernel() {
    int b = blockIdx.x;
    int t = threadIdx.x;
    int lane = t & 31;
    const unsigned F = 0xffffffffu;

    if (t < 32) {   // warp 0 computes the cutoff
        int acc = 0;
        int T = 0;
        for (int hi = NBINS - 1; hi >= 31; hi -= 32) {
            int c = (int)g_hist[b * NBINS + hi - lane];
            int ps = c;
            for (int o = 1; o < 32; o <<= 1) {
                int v = __shfl_up_sync(F, ps, o);
                if (lane >= o) ps += v;
            }
            int tot = __shfl_sync(F, ps, 31);
            unsigned bal = __ballot_sync(F, acc + ps >= K_PRE);
            if (bal) { int l = __ffs(bal) - 1; T = hi - l; break; }
            acc += tot;
        }
        if (lane == 0) { g_T[b] = T; g_cnt[b] = 0; }
    }
    // pre-zero sorted-slot arrays (rank_kernel scatters over these)
    g_sc  [b * K_PRE + t] = make_float2(0.f, 0.f);
    g_bx  [b * K_PRE + t] = make_float4(0.f, 0.f, 0.f, 0.f);
    g_area[b * K_PRE + t] = 0.f;
    __syncthreads();
    // re-zero this batch's histogram for the next graph replay
    #pragma unroll
    for (int r = 0; r < NBINS / 1024; r++)
        g_hist[b * NBINS + r * 1024 + t] = 0u;
}

// ---------------- kernel 3: gather (block-aggregated atomics, 2 keys/thread) ----------------
__global__ void gather_kernel() {
    __shared__ int s_cnt, s_base;
    int b = blockIdx.y;
    int base = (blockIdx.x * blockDim.x + threadIdx.x) * 2;
    if (threadIdx.x == 0) s_cnt = 0;
    __syncthreads();

    uint32_t ks[2] = {0u, 0u};
    int pos[2];
    bool pass[2] = {false, false};

    if (base < NA) {   // NA even -> both lanes valid
        uint2 k2 = *(const uint2*)(g_keys + (size_t)b * NA + base);
        ks[0] = k2.x; ks[1] = k2.y;
        int T = g_T[b];
        #pragma unroll
        for (int u = 0; u < 2; u++) {
            uint32_t key = ks[u];
            if (!key) continue;
            float s = __uint_as_float(key);
            int bin = (int)(s * (float)NBINS);
            if (bin > NBINS - 1) bin = NBINS - 1;
            if (bin < T) continue;
            pos[u] = atomicAdd(&s_cnt, 1);
            pass[u] = true;
        }
    }
    __syncthreads();
    if (threadIdx.x == 0) s_base = (s_cnt > 0) ? atomicAdd(&g_cnt[b], s_cnt) : 0;
    __syncthreads();

    #pragma unroll
    for (int u = 0; u < 2; u++) {
        if (pass[u]) {
            int p = s_base + pos[u];
            if (p < CAP) {
                uint32_t li = (uint32_t)(base + u);
                g_cand[b * CAP + p] =
                    ((unsigned long long)ks[u] << 32) |
                    (unsigned long long)(0xFFFFFFFFu - li);
            }
        }
    }
}

// ---------------- kernel 4: warp-cooperative rank + scatter + box precompute ----------------
// rank(i) = #{j : key_j > key_i}; keys are distinct (composite with ~idx).
// One warp per candidate i; lane l counts over j = l, l+32, l+64, ...
__global__ void __launch_bounds__(256)
rank_kernel(const float* __restrict__ pred) {
    __shared__ unsigned long long sk[CAP];
    int b = blockIdx.y;
    int cnt = g_cnt[b];
    if (cnt > CAP) cnt = CAP;

    int wid  = threadIdx.x >> 5;             // 8 warps/block
    int lane = threadIdx.x & 31;
    int i    = blockIdx.x * 8 + wid;         // candidate handled by this warp
    if ((int)blockIdx.x * 8 >= cnt) return;  // whole block idle

    for (int j = threadIdx.x; j < cnt; j += 256)
        sk[j] = g_cand[b * CAP + j];
    __syncthreads();

    if (i >= cnt) return;
    unsigned long long ki = sk[i];

    int c = 0;
    for (int j = lane; j < cnt; j += 32)      // consecutive 8B lanes: conflict-free
        c += (sk[j] > ki);
    int rank = __reduce_add_sync(0xffffffffu, c);
    if (rank >= K_PRE) return;

    if (lane == 0) {
        float score = __uint_as_float((uint32_t)(ki >> 32));
        uint32_t idx = 0xFFFFFFFFu - (uint32_t)ki;

        const float* pr = pred + ((size_t)b * NA + idx) * NC;
        float cx = pr[0], cy = pr[1], w = pr[2], h = pr[3];
        float x1 = __fsub_rn(cx, __fmul_rn(w, 0.5f));
        float y1 = __fsub_rn(cy, __fmul_rn(h, 0.5f));
        float x2 = __fadd_rn(cx, __fmul_rn(w, 0.5f));
        float y2 = __fadd_rn(cy, __fmul_rn(h, 0.5f));
        float clsf = (float)g_cls[b * NA + idx];
        float off  = __fmul_rn(clsf, MAXWH);

        float ox1 = __fadd_rn(x1, off), oy1 = __fadd_rn(y1, off);
        float ox2 = __fadd_rn(x2, off), oy2 = __fadd_rn(y2, off);

        int s = b * K_PRE + rank;
        g_bx  [s] = make_float4(ox1, oy1, ox2, oy2);
        g_area[s] = __fmul_rn(__fsub_rn(ox2, ox1), __fsub_rn(oy2, oy1));
        g_raw [s] = make_float4(x1, y1, x2, y2);
        g_sc  [s] = make_float2(score, clsf);
    }
}

// ---------------- kernel 5: full-chip suppression mask (64x64 tiles) ----------------
__global__ void mask_kernel() {
    int jt = blockIdx.x;
    int it = blockIdx.y;
    int b  = blockIdx.z;
    int t  = threadIdx.x;
    int i  = it * 64 + t;

    uint32_t w0 = 0u, w1 = 0u;
    if (jt <= it) {
        __shared__ float4 jb[64];
        __shared__ float  ja[64];
        jb[t] = g_bx  [b * K_PRE + jt * 64 + t];
        ja[t] = g_area[b * K_PRE + jt * 64 + t];
        __syncthreads();

        float4 ib = g_bx  [b * K_PRE + i];
        float  ia = g_area[b * K_PRE + i];

        #pragma unroll 8
        for (int jj = 0; jj < 64; jj++) {
            int j = jt * 64 + jj;
            if (j >= i) break;
            float4 ob = jb[jj];
            float ltx = fmaxf(ib.x, ob.x), lty = fmaxf(ib.y, ob.y);
            float rbx = fminf(ib.z, ob.z), rby = fminf(ib.w, ob.w);
            float ww = fmaxf(__fsub_rn(rbx, ltx), 0.0f);
            float hh = fmaxf(__fsub_rn(rby, lty), 0.0f);
            float inter = __fmul_rn(ww, hh);
            float uni   = __fadd_rn(__fsub_rn(__fadd_rn(ia, ja[jj]), inter), 1e-7f);
            float iou   = __fdiv_rn(inter, uni);
            if (iou > IOU_T) {
                if (jj < 32) w0 |= 1u << jj;
                else         w1 |= 1u << (jj - 32);
            }
        }
    }
    g_maskT[(b * 32 + jt * 2 + 0) * K_PRE + i] = w0;
    g_maskT[(b * 32 + jt * 2 + 1) * K_PRE + i] = w1;
}

// ---------------- kernel 6: Jacobi greedy-NMS resolution + output ----------------
__global__ void __launch_bounds__(1024, 1)
final_kernel(float* __restrict__ out) {
    int b = blockIdx.x;
    int t = threadIdx.x;

    __shared__ uint32_t keep_s[32];
    __shared__ int      pfx[33];

    if (t < MAX_DET * 6) out[b * MAX_DET * 6 + t] = 0.0f;

    float2 sc = g_sc[b * K_PRE + t];
    bool valid = sc.x > 0.0f;

    uint32_t row[32];
    #pragma unroll
    for (int w = 0; w < 32; w++) row[w] = g_maskT[(b * 32 + w) * K_PRE + t];

    {
        unsigned bal = __ballot_sync(0xffffffffu, valid);
        if ((t & 31) == 0) keep_s[t >> 5] = bal;
    }
    __syncthreads();

    for (int it = 0; it < K_PRE; it++) {
        uint32_t acc = 0;
        #pragma unroll
        for (int w = 0; w < 32; w++) acc |= row[w] & keep_s[w];
        int nb  = (valid && acc == 0) ? 1 : 0;
        int old = (keep_s[t >> 5] >> (t & 31)) & 1;
        __syncthreads();
        unsigned nbal = __ballot_sync(0xffffffffu, nb);
        if ((t & 31) == 0) keep_s[t >> 5] = nbal;
        int changed = __syncthreads_or(nb != old);
        if (!changed) break;
    }

    if (t == 0) {
        pfx[0] = 0;
        for (int w = 0; w < 32; w++) pfx[w + 1] = pfx[w] + __popc(keep_s[w]);
    }
    __syncthreads();

    uint32_t kw = keep_s[t >> 5];
    if (valid && ((kw >> (t & 31)) & 1)) {
        int rank = pfx[t >> 5] + __popc(kw & ((1u << (t & 31)) - 1u));
        if (rank < MAX_DET) {
            float4 r = g_raw[b * K_PRE + t];
            float* o = out + ((size_t)b * MAX_DET + rank) * 6;
            o[0] = r.x; o[1] = r.y; o[2] = r.z; o[3] = r.w;
            o[4] = sc.x; o[5] = sc.y;
        }
    }
}

// ---------------- launcher ----------------
extern "C" void kernel_launch(void* const* d_in, const int* in_sizes, int n_in,
                              void* d_out, int out_size) {
    (void)in_sizes; (void)n_in; (void)out_size;
    const float* pred = (const float*)d_in[0];
    float* out = (float*)d_out;

    static int configured = 0;
    if (!configured) {
        cudaFuncSetAttribute(score_kernel,
                             cudaFuncAttributeMaxDynamicSharedMemorySize, 2 * TILE_B);
        configured = 1;
    }

    score_kernel <<<SGRID, S_ANCH, 2 * TILE_B>>>(pred);
    thresh_kernel<<<B, 1024>>>();
    gather_kernel<<<dim3((NA / 2 + 255) / 256, B), 256>>>();
    rank_kernel  <<<dim3(CAP / 8, B), 256>>>(pred);
    mask_kernel  <<<dim3(16, 16, B), 64>>>();
    final_kernel <<<B, 1024>>>(out);
}

// round 9
// speedup vs baseline: 3.4561x; 1.0029x over previous
#include <cuda_runtime.h>
#include <cstdint>

#define B       8
#define NA      100800
#define NC      85
#define K_PRE   1024
#define MAX_DET 100
#define NBINS   8192
#define CAP     2048
#define CONF    0.25f
#define IOU_T   0.45f
#define MAXWH   7680.0f

#define S_ANCH   256                        // anchors per tile (== threads per score block)
#define NT       ((B * NA) / S_ANCH)        // 3150 tiles
#define NV       ((S_ANCH * NC) / 4)        // 5440 float4 per tile
#define TILE_B   (S_ANCH * NC * 4)          // 87040 bytes per tile
#define SGRID    148                        // 1 block/SM

// ---------------- device scratch (no allocations allowed) ----------------
__device__ uint32_t           g_keys[B * NA];
__device__ uint8_t            g_cls [B * NA];
__device__ uint32_t           g_hist[B * NBINS];   // zero-init at load; re-zeroed by thresh
__device__ int                g_T   [B];
__device__ int                g_cnt [B];           // zero-init; re-zeroed by thresh
__device__ unsigned long long g_cand[B * CAP];
__device__ float4             g_bx  [B * K_PRE];
__device__ float              g_area[B * K_PRE];
__device__ float4             g_raw [B * K_PRE];
__device__ float2             g_sc  [B * K_PRE];
// suppression bitmask, transposed: word w of row i at [(b*32+w)*1024 + i]
__device__ uint32_t           g_maskT[B * 32 * K_PRE];

// ---------------- cp.async helpers ----------------
__device__ __forceinline__ void cp_async16(uint32_t saddr, const void* gptr) {
    asm volatile("cp.async.cg.shared.global [%0], [%1], 16;" :: "r"(saddr), "l"(gptr));
}
__device__ __forceinline__ void cp_commit() {
    asm volatile("cp.async.commit_group;");
}
template <int N>
__device__ __forceinline__ void cp_wait() {
    asm volatile("cp.async.wait_group %0;" :: "n"(N));
}

// ---------------- kernel 1: score/cls — cp.async double-buffered streaming ----------------
__global__ void __launch_bounds__(S_ANCH)
score_kernel(const float* __restrict__ pred) {
    extern __shared__ float sb[];               // 2 tiles: 174080 B
    int t = threadIdx.x;
    uint32_t sb_u32 = (uint32_t)__cvta_generic_to_shared(sb);

    int tile0 = blockIdx.x;
    if (tile0 < NT) {
        const float4* src = (const float4*)(pred + (size_t)tile0 * (S_ANCH * NC));
        #pragma unroll
        for (int r = 0; r < 22; r++) {
            int i = r * S_ANCH + t;
            if (i < NV) cp_async16(sb_u32 + i * 16, src + i);
        }
        cp_commit();
    }

    int parity = 0;
    for (int tile = tile0; tile < NT; tile += SGRID) {
        int next = tile + SGRID;
        if (next < NT) {
            uint32_t dst = sb_u32 + (parity ^ 1) * TILE_B;
            const float4* src = (const float4*)(pred + (size_t)next * (S_ANCH * NC));
            #pragma unroll
            for (int r = 0; r < 22; r++) {
                int i = r * S_ANCH + t;
                if (i < NV) cp_async16(dst + i * 16, src + i);
            }
            cp_commit();
            cp_wait<1>();
        } else {
            cp_wait<0>();
        }
        __syncthreads();

        const float* p = sb + parity * (S_ANCH * NC) + t * NC;  // stride 85: conflict-free
        float obj = p[4];

        uint32_t key = 0u;
        uint32_t cls = 0u;
        if (obj > CONF) {
            float m0 = -1.f, m1 = -1.f, m2 = -1.f, m3 = -1.f;
            int   i0 = 0,    i1 = 0,    i2 = 0,    i3 = 0;
            #pragma unroll
            for (int k = 0; k < 20; k++) {
                float c0 = __fmul_rn(p[5 + k],      obj);
                float c1 = __fmul_rn(p[5 + 20 + k], obj);
                float c2 = __fmul_rn(p[5 + 40 + k], obj);
                float c3 = __fmul_rn(p[5 + 60 + k], obj);
                if (c0 > m0) { m0 = c0; i0 = k; }
                if (c1 > m1) { m1 = c1; i1 = 20 + k; }
                if (c2 > m2) { m2 = c2; i2 = 40 + k; }
                if (c3 > m3) { m3 = c3; i3 = 60 + k; }
            }
            float best = m0; int bid = i0;
            if (m1 > best) { best = m1; bid = i1; }
            if (m2 > best) { best = m2; bid = i2; }
            if (m3 > best) { best = m3; bid = i3; }

            if (best > CONF) {
                key = __float_as_uint(best);
                cls = (uint32_t)bid;
                int anchor = tile * S_ANCH + t;
                int b = anchor / NA;
                int bin = (int)(best * (float)NBINS);
                if (bin > NBINS - 1) bin = NBINS - 1;
                atomicAdd(&g_hist[b * NBINS + bin], 1u);
            }
        }
        int anchor = tile * S_ANCH + t;
        g_keys[anchor] = key;
        g_cls [anchor] = (uint8_t)cls;

        __syncthreads();
        parity ^= 1;
    }
}

// ---------------- kernel 2: threshold bin + state reset + slot pre-zero ----------------
__global__ void __launch_bounds__(1024)
thresh_kernel() {
    int b = blockIdx.x;
    int t = threadIdx.x;
    int lane = t & 31;
    const unsigned F = 0xffffffffu;

    if (t < 32) {   // warp 0 computes the cutoff
        int acc = 0;
        int T = 0;
        for (int hi = NBINS - 1; hi >= 31; hi -= 32) {
            int c = (int)g_hist[b * NBINS + hi - lane];
            int ps = c;
            for (int o = 1; o < 32; o <<= 1) {
                int v = __shfl_up_sync(F, ps, o);
                if (lane >= o) ps += v;
            }
            int tot = __shfl_sync(F, ps, 31);
            unsigned bal = __ballot_sync(F, acc + ps >= K_PRE);
            if (bal) { int l = __ffs(bal) - 1; T = hi - l; break; }
            acc += tot;
        }
        if (lane == 0) { g_T[b] = T; g_cnt[b] = 0; }
    }
    // pre-zero sorted-slot arrays (rank_kernel scatters over these)
    g_sc  [b * K_PRE + t] = make_float2(0.f, 0.f);
    g_bx  [b * K_PRE + t] = make_float4(0.f, 0.f, 0.f, 0.f);
    g_area[b * K_PRE + t] = 0.f;
    __syncthreads();
    // re-zero this batch's histogram for the next graph replay
    #pragma unroll
    for (int r = 0; r < NBINS / 1024; r++)
        g_hist[b * NBINS + r * 1024 + t] = 0u;
}

// ---------------- kernel 3: gather (block-aggregated atomics, 4 keys/thread) ----------------
__global__ void __launch_bounds__(128)
gather_kernel() {
    __shared__ int s_cnt, s_base;
    int b = blockIdx.y;
    int base = (blockIdx.x * blockDim.x + threadIdx.x) * 4;
    if (threadIdx.x == 0) s_cnt = 0;
    __syncthreads();

    uint32_t ks[4] = {0u, 0u, 0u, 0u};
    int pos[4];
    bool pass[4] = {false, false, false, false};

    if (base < NA) {   // NA % 4 == 0
        uint4 k4 = *(const uint4*)(g_keys + (size_t)b * NA + base);
        ks[0] = k4.x; ks[1] = k4.y; ks[2] = k4.z; ks[3] = k4.w;
        int T = g_T[b];
        #pragma unroll
        for (int u = 0; u < 4; u++) {
            uint32_t key = ks[u];
            if (!key) continue;
            float s = __uint_as_float(key);
            int bin = (int)(s * (float)NBINS);
            if (bin > NBINS - 1) bin = NBINS - 1;
            if (bin < T) continue;
            pos[u] = atomicAdd(&s_cnt, 1);
            pass[u] = true;
        }
    }
    __syncthreads();
    if (threadIdx.x == 0) s_base = (s_cnt > 0) ? atomicAdd(&g_cnt[b], s_cnt) : 0;
    __syncthreads();

    #pragma unroll
    for (int u = 0; u < 4; u++) {
        if (pass[u]) {
            int p = s_base + pos[u];
            if (p < CAP) {
                uint32_t li = (uint32_t)(base + u);
                g_cand[b * CAP + p] =
                    ((unsigned long long)ks[u] << 32) |
                    (unsigned long long)(0xFFFFFFFFu - li);
            }
        }
    }
}

// ---------------- kernel 4: warp-cooperative rank + scatter (32 warps/staging) ----------------
// rank(i) = #{j : key_j > key_i}; keys are distinct (composite with ~idx).
// One warp per candidate; 32 candidates share one block's staged key array.
__global__ void __launch_bounds__(1024)
rank_kernel(const float* __restrict__ pred) {
    __shared__ unsigned long long sk[CAP];
    int b = blockIdx.y;
    int cnt = g_cnt[b];
    if (cnt > CAP) cnt = CAP;

    int wid  = threadIdx.x >> 5;              // 32 warps/block
    int lane = threadIdx.x & 31;
    int i    = blockIdx.x * 32 + wid;          // candidate handled by this warp
    if ((int)blockIdx.x * 32 >= cnt) return;   // whole block idle -> exit before staging

    for (int j = threadIdx.x; j < cnt; j += 1024)
        sk[j] = g_cand[b * CAP + j];
    __syncthreads();

    if (i >= cnt) return;
    unsigned long long ki = sk[i];

    int c = 0;
    for (int j = lane; j < cnt; j += 32)       // consecutive 8B lanes: conflict-free
        c += (sk[j] > ki);
    int rank = __reduce_add_sync(0xffffffffu, c);
    if (rank >= K_PRE) return;

    if (lane == 0) {
        float score = __uint_as_float((uint32_t)(ki >> 32));
        uint32_t idx = 0xFFFFFFFFu - (uint32_t)ki;

        const float* pr = pred + ((size_t)b * NA + idx) * NC;
        float cx = pr[0], cy = pr[1], w = pr[2], h = pr[3];
        float x1 = __fsub_rn(cx, __fmul_rn(w, 0.5f));
        float y1 = __fsub_rn(cy, __fmul_rn(h, 0.5f));
        float x2 = __fadd_rn(cx, __fmul_rn(w, 0.5f));
        float y2 = __fadd_rn(cy, __fmul_rn(h, 0.5f));
        float clsf = (float)g_cls[b * NA + idx];
        float off  = __fmul_rn(clsf, MAXWH);

        float ox1 = __fadd_rn(x1, off), oy1 = __fadd_rn(y1, off);
        float ox2 = __fadd_rn(x2, off), oy2 = __fadd_rn(y2, off);

        int s = b * K_PRE + rank;
        g_bx  [s] = make_float4(ox1, oy1, ox2, oy2);
        g_area[s] = __fmul_rn(__fsub_rn(ox2, ox1), __fsub_rn(oy2, oy1));
        g_raw [s] = make_float4(x1, y1, x2, y2);
        g_sc  [s] = make_float2(score, clsf);
    }
}

// ---------------- kernel 5: full-chip suppression mask (64x64 tiles) ----------------
__global__ void mask_kernel() {
    int jt = blockIdx.x;
    int it = blockIdx.y;
    int b  = blockIdx.z;
    int t  = threadIdx.x;
    int i  = it * 64 + t;

    uint32_t w0 = 0u, w1 = 0u;
    if (jt <= it) {
        __shared__ float4 jb[64];
        __shared__ float  ja[64];
        jb[t] = g_bx  [b * K_PRE + jt * 64 + t];
        ja[t] = g_area[b * K_PRE + jt * 64 + t];
        __syncthreads();

        float4 ib = g_bx  [b * K_PRE + i];
        float  ia = g_area[b * K_PRE + i];

        #pragma unroll 8
        for (int jj = 0; jj < 64; jj++) {
            int j = jt * 64 + jj;
            if (j >= i) break;
            float4 ob = jb[jj];
            float ltx = fmaxf(ib.x, ob.x), lty = fmaxf(ib.y, ob.y);
            float rbx = fminf(ib.z, ob.z), rby = fminf(ib.w, ob.w);
            float ww = fmaxf(__fsub_rn(rbx, ltx), 0.0f);
            float hh = fmaxf(__fsub_rn(rby, lty), 0.0f);
            float inter = __fmul_rn(ww, hh);
            float uni   = __fadd_rn(__fsub_rn(__fadd_rn(ia, ja[jj]), inter), 1e-7f);
            float iou   = __fdiv_rn(inter, uni);
            if (iou > IOU_T) {
                if (jj < 32) w0 |= 1u << jj;
                else         w1 |= 1u << (jj - 32);
            }
        }
    }
    g_maskT[(b * 32 + jt * 2 + 0) * K_PRE + i] = w0;
    g_maskT[(b * 32 + jt * 2 + 1) * K_PRE + i] = w1;
}

// ---------------- kernel 6: Jacobi greedy-NMS resolution + output ----------------
__global__ void __launch_bounds__(1024, 1)
final_kernel(float* __restrict__ out) {
    int b = blockIdx.x;
    int t = threadIdx.x;

    __shared__ uint32_t keep_s[32];
    __shared__ int      pfx[33];

    if (t < MAX_DET * 6) out[b * MAX_DET * 6 + t] = 0.0f;

    float2 sc = g_sc[b * K_PRE + t];
    bool valid = sc.x > 0.0f;

    uint32_t row[32];
    #pragma unroll
    for (int w = 0; w < 32; w++) row[w] = g_maskT[(b * 32 + w) * K_PRE + t];

    {
        unsigned bal = __ballot_sync(0xffffffffu, valid);
        if ((t & 31) == 0) keep_s[t >> 5] = bal;
    }
    __syncthreads();

    for (int it = 0; it < K_PRE; it++) {
        uint32_t acc = 0;
        #pragma unroll
        for (int w = 0; w < 32; w++) acc |= row[w] & keep_s[w];
        int nb  = (valid && acc == 0) ? 1 : 0;
        int old = (keep_s[t >> 5] >> (t & 31)) & 1;
        __syncthreads();
        unsigned nbal = __ballot_sync(0xffffffffu, nb);
        if ((t & 31) == 0) keep_s[t >> 5] = nbal;
        int changed = __syncthreads_or(nb != old);
        if (!changed) break;
    }

    if (t == 0) {
        pfx[0] = 0;
        for (int w = 0; w < 32; w++) pfx[w + 1] = pfx[w] + __popc(keep_s[w]);
    }
    __syncthreads();

    uint32_t kw = keep_s[t >> 5];
    if (valid && ((kw >> (t & 31)) & 1)) {
        int rank = pfx[t >> 5] + __popc(kw & ((1u << (t & 31)) - 1u));
        if (rank < MAX_DET) {
            float4 r = g_raw[b * K_PRE + t];
            float* o = out + ((size_t)b * MAX_DET + rank) * 6;
            o[0] = r.x; o[1] = r.y; o[2] = r.z; o[3] = r.w;
            o[4] = sc.x; o[5] = sc.y;
        }
    }
}

// ---------------- launcher ----------------
extern "C" void kernel_launch(void* const* d_in, const int* in_sizes, int n_in,
                              void* d_out, int out_size) {
    (void)in_sizes; (void)n_in; (void)out_size;
    const float* pred = (const float*)d_in[0];
    float* out = (float*)d_out;

    static int configured = 0;
    if (!configured) {
        cudaFuncSetAttribute(score_kernel,
                             cudaFuncAttributeMaxDynamicSharedMemorySize, 2 * TILE_B);
        configured = 1;
    }

    score_kernel <<<SGRID, S_ANCH, 2 * TILE_B>>>(pred);
    thresh_kernel<<<B, 1024>>>();
    gather_kernel<<<dim3((NA / 4 + 127) / 128, B), 128>>>();
    rank_kernel  <<<dim3(CAP / 32, B), 1024>>>(pred);
    mask_kernel  <<<dim3(16, 16, B), 64>>>();
    final_kernel <<<B, 1024>>>(out);
}

// round 10
// speedup vs baseline: 3.4853x; 1.0084x over previous
#include <cuda_runtime.h>
#include <cstdint>

#define B       8
#define NA      100800
#define NC      85
#define K_PRE   1024
#define MAX_DET 100
#define NBINS   8192
#define CAP     2048
#define CONF    0.25f
#define IOU_T   0.45f
#define MAXWH   7680.0f

#define S_ANCH   256                        // anchors per tile (== threads per score block)
#define NT       ((B * NA) / S_ANCH)        // 3150 tiles
#define TILE_B   (S_ANCH * NC * 4)          // 87040 bytes per tile
#define SGRID    148                        // 1 block/SM

// ---------------- device scratch (no allocations allowed) ----------------
__device__ uint32_t           g_keys[B * NA];
__device__ uint8_t            g_cls [B * NA];
__device__ uint32_t           g_hist[B * NBINS];   // zero-init at load; re-zeroed by thresh
__device__ int                g_T   [B];
__device__ int                g_cnt [B];           // zero-init; re-zeroed by thresh
__device__ unsigned long long g_cand[B * CAP];
__device__ float4             g_bx  [B * K_PRE];
__device__ float              g_area[B * K_PRE];
__device__ float4             g_raw [B * K_PRE];
__device__ float2             g_sc  [B * K_PRE];
// suppression bitmask, transposed: word w of row i at [(b*32+w)*1024 + i]
__device__ uint32_t           g_maskT[B * 32 * K_PRE];

// ---------------- mbarrier / TMA-bulk helpers ----------------
__device__ __forceinline__ uint32_t smem_u32(const void* p) {
    return (uint32_t)__cvta_generic_to_shared(p);
}
__device__ __forceinline__ void mbar_init(uint32_t mbar, uint32_t count) {
    asm volatile("mbarrier.init.shared.b64 [%0], %1;" :: "r"(mbar), "r"(count) : "memory");
}
__device__ __forceinline__ void mbar_expect_tx(uint32_t mbar, uint32_t bytes) {
    asm volatile("mbarrier.arrive.expect_tx.shared.b64 _, [%0], %1;"
                 :: "r"(mbar), "r"(bytes) : "memory");
}
__device__ __forceinline__ void bulk_g2s(uint32_t dst, const void* src,
                                         uint32_t bytes, uint32_t mbar) {
    asm volatile("cp.async.bulk.shared::cta.global.mbarrier::complete_tx::bytes "
                 "[%0], [%1], %2, [%3];"
                 :: "r"(dst), "l"(src), "r"(bytes), "r"(mbar) : "memory");
}
__device__ __forceinline__ void mbar_wait(uint32_t mbar, uint32_t phase) {
    uint32_t done;
    asm volatile(
        "{\n\t.reg .pred p;\n\t"
        "mbarrier.try_wait.parity.acquire.cta.shared::cta.b64 p, [%1], %2;\n\t"
        "selp.b32 %0, 1, 0, p;\n\t}"
        : "=r"(done) : "r"(mbar), "r"(phase) : "memory");
    if (!done) {
        asm volatile(
            "{\n\t.reg .pred P1;\n\t"
            "WL_%=:\n\t"
            "mbarrier.try_wait.parity.acquire.cta.shared::cta.b64 P1, [%0], %1, 0x989680;\n\t"
            "@P1 bra.uni WD_%=;\n\t"
            "bra.uni WL_%=;\n\t"
            "WD_%=:\n\t}"
            :: "r"(mbar), "r"(phase) : "memory");
    }
}

// ---------------- kernel 1: score/cls — TMA-bulk double-buffered streaming ----------------
__global__ void __launch_bounds__(S_ANCH)
score_kernel(const float* __restrict__ pred) {
    extern __shared__ float sb[];               // 2 tiles: 174080 B
    __shared__ alignas(8) unsigned long long barst[2];
    int t = threadIdx.x;
    uint32_t sb_u32  = smem_u32(sb);
    uint32_t bar_u32 = smem_u32(barst);

    if (t == 0) { mbar_init(bar_u32, 1); mbar_init(bar_u32 + 8, 1); }
    __syncthreads();

    int tile0 = blockIdx.x;
    if (tile0 < NT && t == 0) {
        mbar_expect_tx(bar_u32, TILE_B);
        bulk_g2s(sb_u32, pred + (size_t)tile0 * (S_ANCH * NC), TILE_B, bar_u32);
    }

    int ph0 = 0, ph1 = 0;
    int parity = 0;
    for (int tile = tile0; tile < NT; tile += SGRID) {
        int next = tile + SGRID;
        if (next < NT && t == 0) {
            uint32_t b2 = bar_u32 + (parity ^ 1) * 8;
            mbar_expect_tx(b2, TILE_B);
            bulk_g2s(sb_u32 + (parity ^ 1) * TILE_B,
                     pred + (size_t)next * (S_ANCH * NC), TILE_B, b2);
        }
        // wait for current tile
        if (parity == 0) { mbar_wait(bar_u32,     ph0); ph0 ^= 1; }
        else             { mbar_wait(bar_u32 + 8, ph1); ph1 ^= 1; }

        // ---- compute current tile (identical arithmetic to prior rounds) ----
        const float* p = sb + parity * (S_ANCH * NC) + t * NC;  // stride 85: conflict-free
        float obj = p[4];

        uint32_t key = 0u;
        uint32_t cls = 0u;
        if (obj > CONF) {
            float m0 = -1.f, m1 = -1.f, m2 = -1.f, m3 = -1.f;
            int   i0 = 0,    i1 = 0,    i2 = 0,    i3 = 0;
            #pragma unroll
            for (int k = 0; k < 20; k++) {
                float c0 = __fmul_rn(p[5 + k],      obj);
                float c1 = __fmul_rn(p[5 + 20 + k], obj);
                float c2 = __fmul_rn(p[5 + 40 + k], obj);
                float c3 = __fmul_rn(p[5 + 60 + k], obj);
                if (c0 > m0) { m0 = c0; i0 = k; }
                if (c1 > m1) { m1 = c1; i1 = 20 + k; }
                if (c2 > m2) { m2 = c2; i2 = 40 + k; }
                if (c3 > m3) { m3 = c3; i3 = 60 + k; }
            }
            float best = m0; int bid = i0;
            if (m1 > best) { best = m1; bid = i1; }
            if (m2 > best) { best = m2; bid = i2; }
            if (m3 > best) { best = m3; bid = i3; }

            if (best > CONF) {
                key = __float_as_uint(best);
                cls = (uint32_t)bid;
                int anchor = tile * S_ANCH + t;
                int b = anchor / NA;
                int bin = (int)(best * (float)NBINS);
                if (bin > NBINS - 1) bin = NBINS - 1;
                atomicAdd(&g_hist[b * NBINS + bin], 1u);
            }
        }
        int anchor = tile * S_ANCH + t;
        g_keys[anchor] = key;
        g_cls [anchor] = (uint8_t)cls;

        __syncthreads();      // all threads done with this buffer before it is refilled
        parity ^= 1;
    }
}

// ---------------- kernel 2: threshold bin + state reset + slot pre-zero ----------------
__global__ void __launch_bounds__(1024)
thresh_kernel() {
    int b = blockIdx.x;
    int t = threadIdx.x;
    int lane = t & 31;
    const unsigned F = 0xffffffffu;

    if (t < 32) {   // warp 0 computes the cutoff
        int acc = 0;
        int T = 0;
        for (int hi = NBINS - 1; hi >= 31; hi -= 32) {
            int c = (int)g_hist[b * NBINS + hi - lane];
            int ps = c;
            for (int o = 1; o < 32; o <<= 1) {
                int v = __shfl_up_sync(F, ps, o);
                if (lane >= o) ps += v;
            }
            int tot = __shfl_sync(F, ps, 31);
            unsigned bal = __ballot_sync(F, acc + ps >= K_PRE);
            if (bal) { int l = __ffs(bal) - 1; T = hi - l; break; }
            acc += tot;
        }
        if (lane == 0) { g_T[b] = T; g_cnt[b] = 0; }
    }
    // pre-zero sorted-slot arrays (rank_kernel scatters over these)
    g_sc  [b * K_PRE + t] = make_float2(0.f, 0.f);
    g_bx  [b * K_PRE + t] = make_float4(0.f, 0.f, 0.f, 0.f);
    g_area[b * K_PRE + t] = 0.f;
    __syncthreads();
    // re-zero this batch's histogram for the next graph replay
    #pragma unroll
    for (int r = 0; r < NBINS / 1024; r++)
        g_hist[b * NBINS + r * 1024 + t] = 0u;
}

// ---------------- kernel 3: gather (block-aggregated atomics, 4 keys/thread) ----------------
__global__ void __launch_bounds__(128)
gather_kernel() {
    __shared__ int s_cnt, s_base;
    int b = blockIdx.y;
    int base = (blockIdx.x * blockDim.x + threadIdx.x) * 4;
    if (threadIdx.x == 0) s_cnt = 0;
    __syncthreads();

    uint32_t ks[4] = {0u, 0u, 0u, 0u};
    int pos[4];
    bool pass[4] = {false, false, false, false};

    if (base < NA) {   // NA % 4 == 0
        uint4 k4 = *(const uint4*)(g_keys + (size_t)b * NA + base);
        ks[0] = k4.x; ks[1] = k4.y; ks[2] = k4.z; ks[3] = k4.w;
        int T = g_T[b];
        #pragma unroll
        for (int u = 0; u < 4; u++) {
            uint32_t key = ks[u];
            if (!key) continue;
            float s = __uint_as_float(key);
            int bin = (int)(s * (float)NBINS);
            if (bin > NBINS - 1) bin = NBINS - 1;
            if (bin < T) continue;
            pos[u] = atomicAdd(&s_cnt, 1);
            pass[u] = true;
        }
    }
    __syncthreads();
    if (threadIdx.x == 0) s_base = (s_cnt > 0) ? atomicAdd(&g_cnt[b], s_cnt) : 0;
    __syncthreads();

    #pragma unroll
    for (int u = 0; u < 4; u++) {
        if (pass[u]) {
            int p = s_base + pos[u];
            if (p < CAP) {
                uint32_t li = (uint32_t)(base + u);
                g_cand[b * CAP + p] =
                    ((unsigned long long)ks[u] << 32) |
                    (unsigned long long)(0xFFFFFFFFu - li);
            }
        }
    }
}

// ---------------- kernel 4: warp-cooperative rank + scatter (padded, unrolled) ----------------
// rank(i) = #{j : key_j > key_i}; keys distinct. Pad with key=0 (never > real key).
__global__ void __launch_bounds__(1024)
rank_kernel(const float* __restrict__ pred) {
    __shared__ unsigned long long sk[CAP];
    int b = blockIdx.y;
    int cnt = g_cnt[b];
    if (cnt > CAP) cnt = CAP;
    int cntP = (cnt + 127) & ~127;             // pad to multiple of 128

    int wid  = threadIdx.x >> 5;               // 32 warps/block
    int lane = threadIdx.x & 31;
    int i    = blockIdx.x * 32 + wid;
    if ((int)blockIdx.x * 32 >= cnt) return;    // whole block idle

    for (int j = threadIdx.x; j < cntP; j += 1024)
        sk[j] = (j < cnt) ? g_cand[b * CAP + j] : 0ull;
    __syncthreads();

    if (i >= cnt) return;
    unsigned long long ki = sk[i];

    int c = 0;
    for (int j = lane; j < cntP; j += 128) {    // 4x unrolled, conflict-free
        c += (sk[j]      > ki);
        c += (sk[j + 32] > ki);
        c += (sk[j + 64] > ki);
        c += (sk[j + 96] > ki);
    }
    int rank = __reduce_add_sync(0xffffffffu, c);
    if (rank >= K_PRE) return;

    if (lane == 0) {
        float score = __uint_as_float((uint32_t)(ki >> 32));
        uint32_t idx = 0xFFFFFFFFu - (uint32_t)ki;

        const float* pr = pred + ((size_t)b * NA + idx) * NC;
        float cx = pr[0], cy = pr[1], w = pr[2], h = pr[3];
        float x1 = __fsub_rn(cx, __fmul_rn(w, 0.5f));
        float y1 = __fsub_rn(cy, __fmul_rn(h, 0.5f));
        float x2 = __fadd_rn(cx, __fmul_rn(w, 0.5f));
        float y2 = __fadd_rn(cy, __fmul_rn(h, 0.5f));
        float clsf = (float)g_cls[b * NA + idx];
        float off  = __fmul_rn(clsf, MAXWH);

        float ox1 = __fadd_rn(x1, off), oy1 = __fadd_rn(y1, off);
        float ox2 = __fadd_rn(x2, off), oy2 = __fadd_rn(y2, off);

        int s = b * K_PRE + rank;
        g_bx  [s] = make_float4(ox1, oy1, ox2, oy2);
        g_area[s] = __fmul_rn(__fsub_rn(ox2, ox1), __fsub_rn(oy2, oy1));
        g_raw [s] = make_float4(x1, y1, x2, y2);
        g_sc  [s] = make_float2(score, clsf);
    }
}

// ---------------- kernel 5: full-chip suppression mask (64x64 tiles) ----------------
__global__ void mask_kernel() {
    int jt = blockIdx.x;
    int it = blockIdx.y;
    int b  = blockIdx.z;
    int t  = threadIdx.x;
    int i  = it * 64 + t;

    uint32_t w0 = 0u, w1 = 0u;
    if (jt <= it) {
        __shared__ float4 jb[64];
        __shared__ float  ja[64];
        jb[t] = g_bx  [b * K_PRE + jt * 64 + t];
        ja[t] = g_area[b * K_PRE + jt * 64 + t];
        __syncthreads();

        float4 ib = g_bx  [b * K_PRE + i];
        float  ia = g_area[b * K_PRE + i];

        #pragma unroll 8
        for (int jj = 0; jj < 64; jj++) {
            int j = jt * 64 + jj;
            if (j >= i) break;
            float4 ob = jb[jj];
            float ltx = fmaxf(ib.x, ob.x), lty = fmaxf(ib.y, ob.y);
            float rbx = fminf(ib.z, ob.z), rby = fminf(ib.w, ob.w);
            float ww = fmaxf(__fsub_rn(rbx, ltx), 0.0f);
            float hh = fmaxf(__fsub_rn(rby, lty), 0.0f);
            float inter = __fmul_rn(ww, hh);
            float uni   = __fadd_rn(__fsub_rn(__fadd_rn(ia, ja[jj]), inter), 1e-7f);
            float iou   = __fdiv_rn(inter, uni);
            if (iou > IOU_T) {
                if (jj < 32) w0 |= 1u << jj;
                else         w1 |= 1u << (jj - 32);
            }
        }
    }
    g_maskT[(b * 32 + jt * 2 + 0) * K_PRE + i] = w0;
    g_maskT[(b * 32 + jt * 2 + 1) * K_PRE + i] = w1;
}

// ---------------- kernel 6: Jacobi greedy-NMS resolution + output ----------------
__global__ void __launch_bounds__(1024, 1)
final_kernel(float* __restrict__ out) {
    int b = blockIdx.x;
    int t = threadIdx.x;

    __shared__ uint32_t keep_s[32];
    __shared__ int      pfx[33];

    if (t < MAX_DET * 6) out[b * MAX_DET * 6 + t] = 0.0f;

    float2 sc = g_sc[b * K_PRE + t];
    bool valid = sc.x > 0.0f;

    uint32_t row[32];
    #pragma unroll
    for (int w = 0; w < 32; w++) row[w] = g_maskT[(b * 32 + w) * K_PRE + t];

    {
        unsigned bal = __ballot_sync(0xffffffffu, valid);
        if ((t & 31) == 0) keep_s[t >> 5] = bal;
    }
    __syncthreads();

    for (int it = 0; it < K_PRE; it++) {
        uint32_t acc = 0;
        #pragma unroll
        for (int w = 0; w < 32; w++) acc |= row[w] & keep_s[w];
        int nb  = (valid && acc == 0) ? 1 : 0;
        int old = (keep_s[t >> 5] >> (t & 31)) & 1;
        __syncthreads();
        unsigned nbal = __ballot_sync(0xffffffffu, nb);
        if ((t & 31) == 0) keep_s[t >> 5] = nbal;
        int changed = __syncthreads_or(nb != old);
        if (!changed) break;
    }

    if (t == 0) {
        pfx[0] = 0;
        for (int w = 0; w < 32; w++) pfx[w + 1] = pfx[w] + __popc(keep_s[w]);
    }
    __syncthreads();

    uint32_t kw = keep_s[t >> 5];
    if (valid && ((kw >> (t & 31)) & 1)) {
        int rank = pfx[t >> 5] + __popc(kw & ((1u << (t & 31)) - 1u));
        if (rank < MAX_DET) {
            float4 r = g_raw[b * K_PRE + t];
            float* o = out + ((size_t)b * MAX_DET + rank) * 6;
            o[0] = r.x; o[1] = r.y; o[2] = r.z; o[3] = r.w;
            o[4] = sc.x; o[5] = sc.y;
        }
    }
}

// ---------------- launcher ----------------
extern "C" void kernel_launch(void* const* d_in, const int* in_sizes, int n_in,
                              void* d_out, int out_size) {
    (void)in_sizes; (void)n_in; (void)out_size;
    const float* pred = (const float*)d_in[0];
    float* out = (float*)d_out;

    static int configured = 0;
    if (!configured) {
        cudaFuncSetAttribute(score_kernel,
                             cudaFuncAttributeMaxDynamicSharedMemorySize, 2 * TILE_B);
        configured = 1;
    }

    score_kernel <<<SGRID, S_ANCH, 2 * TILE_B>>>(pred);
    thresh_kernel<<<B, 1024>>>();
    gather_kernel<<<dim3((NA / 4 + 127) / 128, B), 128>>>();
    rank_kernel  <<<dim3(CAP / 32, B), 1024>>>(pred);
    mask_kernel  <<<dim3(16, 16, B), 64>>>();
    final_kernel <<<B, 1024>>>(out);
}